// round 1
// baseline (speedup 1.0000x reference)
#include <cuda_runtime.h>
#include <math.h>

// ---------------- problem constants ----------------
#define BB   32
#define NN   512
#define IND  128
#define HID  256
#define HID2 512
#define HEADS 4
#define HD   64
#define ACT  32
#define TOK  (BB*NN)            // 16384 tokens

// ---------------- scratch (device globals; no allocation allowed) --------
__device__ float g_h1[TOK * HID2];      // encoder mid (16384x512)
__device__ float g_hsp[TOK * HID];      // h_spatial
__device__ float g_Wh[TOK * HID];       // GAT per-head projection
__device__ float g_hl[BB * HEADS * NN]; // left scores
__device__ float g_hr[BB * HEADS * NN]; // right scores
__device__ float g_aout[TOK * HID];     // attention output
__device__ float g_hattn[TOK * HID];    // after out-proj + skip
__device__ float g_gi[TOK * 3 * HID];   // GRU input gates
__device__ float g_gh[TOK * 3 * HID];   // GRU hidden gates
__device__ float g_q[TOK * HID];        // decoder mid

// ---------------- generic NT GEMM: C[M,N] = A[M,K] @ W[N,K]^T (+b1[n]) (+b2[n]) ---
// BM=BN=64, BK=16, 256 threads, 4x4 per-thread microtile.
__global__ void gemm_nt_kernel(const float* __restrict__ A,
                               const float* __restrict__ W,
                               const float* __restrict__ b1,
                               const float* __restrict__ b2,
                               float* __restrict__ C,
                               int M, int N, int K, int accum)
{
    __shared__ float As[16][68];
    __shared__ float Ws[16][68];

    const int m0 = blockIdx.y * 64;
    const int n0 = blockIdx.x * 64;
    const int tid = threadIdx.x;

    const int lr = tid >> 2;        // 0..63 (row within tile)
    const int lk = (tid & 3) * 4;   // 0,4,8,12 (k offset)

    float acc[4][4];
#pragma unroll
    for (int i = 0; i < 4; i++)
#pragma unroll
        for (int j = 0; j < 4; j++) acc[i][j] = 0.f;

    const int ty = tid >> 4;   // 0..15 -> m
    const int tx = tid & 15;   // 0..15 -> n

    for (int k0 = 0; k0 < K; k0 += 16) {
        // load A tile (M always multiple of 64 here)
        float4 av = *reinterpret_cast<const float4*>(A + (size_t)(m0 + lr) * K + k0 + lk);
        As[lk + 0][lr] = av.x;
        As[lk + 1][lr] = av.y;
        As[lk + 2][lr] = av.z;
        As[lk + 3][lr] = av.w;
        // load W tile (guard N)
        int wn = n0 + lr;
        float4 wv = make_float4(0.f, 0.f, 0.f, 0.f);
        if (wn < N)
            wv = *reinterpret_cast<const float4*>(W + (size_t)wn * K + k0 + lk);
        Ws[lk + 0][lr] = wv.x;
        Ws[lk + 1][lr] = wv.y;
        Ws[lk + 2][lr] = wv.z;
        Ws[lk + 3][lr] = wv.w;
        __syncthreads();

#pragma unroll
        for (int kk = 0; kk < 16; kk++) {
            float4 a = *reinterpret_cast<const float4*>(&As[kk][ty * 4]);
            float4 b = *reinterpret_cast<const float4*>(&Ws[kk][tx * 4]);
            acc[0][0] += a.x * b.x; acc[0][1] += a.x * b.y; acc[0][2] += a.x * b.z; acc[0][3] += a.x * b.w;
            acc[1][0] += a.y * b.x; acc[1][1] += a.y * b.y; acc[1][2] += a.y * b.z; acc[1][3] += a.y * b.w;
            acc[2][0] += a.z * b.x; acc[2][1] += a.z * b.y; acc[2][2] += a.z * b.z; acc[2][3] += a.z * b.w;
            acc[3][0] += a.w * b.x; acc[3][1] += a.w * b.y; acc[3][2] += a.w * b.z; acc[3][3] += a.w * b.w;
        }
        __syncthreads();
    }

#pragma unroll
    for (int i = 0; i < 4; i++) {
        int m = m0 + ty * 4 + i;
#pragma unroll
        for (int j = 0; j < 4; j++) {
            int n = n0 + tx * 4 + j;
            if (n < N) {
                float v = acc[i][j];
                if (b1) v += b1[n];
                if (b2) v += b2[n];
                size_t idx = (size_t)m * N + n;
                if (accum) C[idx] += v;
                else       C[idx]  = v;
            }
        }
    }
}

// ---------------- fused LayerNorm + exact GELU (in place), D = 256 or 512 ----
__device__ __forceinline__ float gelu_exact(float x) {
    return 0.5f * x * (1.0f + erff(x * 0.70710678118654752440f));
}

__global__ void ln_gelu_kernel(float* __restrict__ X,
                               const float* __restrict__ g,
                               const float* __restrict__ b,
                               int D)
{
    __shared__ float red[256];
    float* row = X + (size_t)blockIdx.x * D;
    const int t = threadIdx.x;

    float v0 = row[t];
    float v1 = (D > 256) ? row[t + 256] : 0.f;

    red[t] = v0 + v1;
    __syncthreads();
    for (int o = 128; o; o >>= 1) { if (t < o) red[t] += red[t + o]; __syncthreads(); }
    float mean = red[0] / (float)D;
    __syncthreads();

    float d0 = v0 - mean;
    float d1 = v1 - mean;
    float sq = d0 * d0 + ((D > 256) ? d1 * d1 : 0.f);
    red[t] = sq;
    __syncthreads();
    for (int o = 128; o; o >>= 1) { if (t < o) red[t] += red[t + o]; __syncthreads(); }
    float var = red[0] / (float)D;
    float rstd = rsqrtf(var + 1e-5f);

    row[t] = gelu_exact(d0 * rstd * g[t] + b[t]);
    if (D > 256)
        row[t + 256] = gelu_exact(d1 * rstd * g[t + 256] + b[t + 256]);
}

// ---------------- GAT left/right scores: hl/hr[(b*4+h)*512 + i] --------------
__global__ void lr_kernel(const float* __restrict__ Wh,
                          const float* __restrict__ a,
                          float* __restrict__ hl,
                          float* __restrict__ hr)
{
    const int token = blockIdx.x;             // 0..16383
    const int w = threadIdx.x >> 5;           // 0..7
    const int lane = threadIdx.x & 31;
    const int head = w >> 1;
    const int side = w & 1;

    const float* whp = Wh + (size_t)token * HID + head * HD;
    const float* ap = a + head * (2 * HD) + side * HD;
    float s = whp[lane] * ap[lane] + whp[lane + 32] * ap[lane + 32];
#pragma unroll
    for (int o = 16; o; o >>= 1) s += __shfl_xor_sync(0xffffffffu, s, o);
    if (lane == 0) {
        int bidx = token >> 9;          // /512
        int i = token & 511;
        float* dst = side ? hr : hl;
        dst[((bidx * HEADS + head) << 9) + i] = s;
    }
}

// ---------------- fused GAT masked-softmax + AV ------------------------------
// block = 256 threads = 8 warps, each warp owns one row i of one (b,h);
// warps in a block share the same (b,h) Wh slab -> L1 reuse.
__global__ void gat_attn_kernel(const float* __restrict__ Wh,
                                const float* __restrict__ hl,
                                const float* __restrict__ hr,
                                const int* __restrict__ adj,
                                float* __restrict__ out)
{
    const int blk = blockIdx.x;            // 32*4*64 = 8192
    const int itile = blk & 63;
    const int h = (blk >> 6) & 3;
    const int b = blk >> 8;
    const int w = threadIdx.x >> 5;
    const int lane = threadIdx.x & 31;
    const int i = itile * 8 + w;

    const float l = hl[((b * HEADS + h) << 9) + i];
    const float* rv = hr + ((b * HEADS + h) << 9);
    const int* mrow = adj + ((size_t)b * NN + i) * NN;
    const float* whb = Wh + (size_t)b * NN * HID + h * HD;

    // pass 1: masked row max (leaky-relu applied pre-mask, monotone recompute)
    float mx = -INFINITY;
    for (int j = lane; j < NN; j += 32) {
        if (mrow[j]) {
            float e = l + rv[j];
            e = (e >= 0.f) ? e : 0.2f * e;
            mx = fmaxf(mx, e);
        }
    }
#pragma unroll
    for (int o = 16; o; o >>= 1) mx = fmaxf(mx, __shfl_xor_sync(0xffffffffu, mx, o));

    // pass 2: weights + weighted sum of Wh rows (float2 per lane = 64 cols)
    float s = 0.f;
    float2 acc = make_float2(0.f, 0.f);
    for (int j0 = 0; j0 < NN; j0 += 32) {
        int j = j0 + lane;
        float wgt = 0.f;
        if (mrow[j]) {
            float e = l + rv[j];
            e = (e >= 0.f) ? e : 0.2f * e;
            wgt = expf(e - mx);
        }
        s += wgt;
#pragma unroll
        for (int jj = 0; jj < 32; jj++) {
            float wv = __shfl_sync(0xffffffffu, wgt, jj);
            const float2* wr = reinterpret_cast<const float2*>(whb + (size_t)(j0 + jj) * HID);
            float2 v = wr[lane];
            acc.x += wv * v.x;
            acc.y += wv * v.y;
        }
    }
#pragma unroll
    for (int o = 16; o; o >>= 1) s += __shfl_xor_sync(0xffffffffu, s, o);
    float inv = 1.f / s;

    float2* op = reinterpret_cast<float2*>(out + (size_t)(b * NN + i) * HID + h * HD);
    op[lane] = make_float2(acc.x * inv, acc.y * inv);
}

// ---------------- GRU gates -> h_temp (written straight to output) ----------
__global__ void gru_kernel(const float* __restrict__ gi,
                           const float* __restrict__ gh,
                           const float* __restrict__ hidden,
                           float* __restrict__ h_temp)
{
    int idx = blockIdx.x * blockDim.x + threadIdx.x;   // TOK*HID
    if (idx >= TOK * HID) return;
    int row = idx / HID;
    int c = idx - row * HID;
    const float* gir = gi + (size_t)row * (3 * HID);
    const float* ghr = gh + (size_t)row * (3 * HID);
    float r = 1.f / (1.f + expf(-(gir[c] + ghr[c])));
    float z = 1.f / (1.f + expf(-(gir[HID + c] + ghr[HID + c])));
    float n = tanhf(gir[2 * HID + c] + r * ghr[2 * HID + c]);
    float hprev = hidden[idx];
    h_temp[idx] = (1.f - z) * n + z * hprev;
}

// ---------------- launch ----------------
extern "C" void kernel_launch(void* const* d_in, const int* in_sizes, int n_in,
                              void* d_out, int out_size)
{
    const float* x        = (const float*)d_in[0];
    const int*   adj      = (const int*)  d_in[1];
    const float* hidden   = (const float*)d_in[2];
    const float* enc_w1   = (const float*)d_in[3];
    const float* enc_b1   = (const float*)d_in[4];
    const float* ln1_g    = (const float*)d_in[5];
    const float* ln1_b    = (const float*)d_in[6];
    const float* enc_w2   = (const float*)d_in[7];
    const float* enc_b2   = (const float*)d_in[8];
    const float* pos      = (const float*)d_in[9];
    const float* gat_w    = (const float*)d_in[10];
    const float* gat_b    = (const float*)d_in[11];
    const float* gat_a    = (const float*)d_in[12];
    const float* gat_ow   = (const float*)d_in[13];
    const float* gat_ob   = (const float*)d_in[14];
    const float* skip_w   = (const float*)d_in[15];
    const float* skip_b   = (const float*)d_in[16];
    const float* gru_wih  = (const float*)d_in[17];
    const float* gru_bih  = (const float*)d_in[18];
    const float* gru_whh  = (const float*)d_in[19];
    const float* gru_bhh  = (const float*)d_in[20];
    const float* dec_w1   = (const float*)d_in[21];
    const float* dec_b1   = (const float*)d_in[22];
    const float* ln2_g    = (const float*)d_in[23];
    const float* ln2_b    = (const float*)d_in[24];
    const float* dec_w2   = (const float*)d_in[25];
    const float* dec_b2   = (const float*)d_in[26];

    float* out = (float*)d_out;
    float* q_out = out;                       // (B,N,ACT) = 524288 floats
    float* h_temp_out = out + (size_t)TOK * ACT;  // (B,N,HID)

    float *h1, *hsp, *Wh, *hl, *hr, *aout, *hattn, *gi, *gh, *q;
    cudaGetSymbolAddress((void**)&h1,    g_h1);
    cudaGetSymbolAddress((void**)&hsp,   g_hsp);
    cudaGetSymbolAddress((void**)&Wh,    g_Wh);
    cudaGetSymbolAddress((void**)&hl,    g_hl);
    cudaGetSymbolAddress((void**)&hr,    g_hr);
    cudaGetSymbolAddress((void**)&aout,  g_aout);
    cudaGetSymbolAddress((void**)&hattn, g_hattn);
    cudaGetSymbolAddress((void**)&gi,    g_gi);
    cudaGetSymbolAddress((void**)&gh,    g_gh);
    cudaGetSymbolAddress((void**)&q,     g_q);

    const int MB = TOK / 64;   // 256 row-blocks

    // encoder: Linear(128->512) -> LN -> GELU -> Linear(512->256) + pos
    gemm_nt_kernel<<<dim3(HID2 / 64, MB), 256>>>(x, enc_w1, enc_b1, nullptr, h1, TOK, HID2, IND, 0);
    ln_gelu_kernel<<<TOK, 256>>>(h1, ln1_g, ln1_b, HID2);
    gemm_nt_kernel<<<dim3(HID / 64, MB), 256>>>(h1, enc_w2, enc_b2, pos, hsp, TOK, HID, HID2, 0);

    // GAT
    gemm_nt_kernel<<<dim3(HID / 64, MB), 256>>>(hsp, gat_w, gat_b, nullptr, Wh, TOK, HID, HID, 0);
    lr_kernel<<<TOK, 256>>>(Wh, gat_a, hl, hr);
    gat_attn_kernel<<<BB * HEADS * (NN / 8), 256>>>(Wh, hl, hr, adj, aout);

    // out-proj + skip (accumulated second GEMM)
    gemm_nt_kernel<<<dim3(HID / 64, MB), 256>>>(aout, gat_ow, gat_ob, skip_b, hattn, TOK, HID, HID, 0);
    gemm_nt_kernel<<<dim3(HID / 64, MB), 256>>>(hsp, skip_w, nullptr, nullptr, hattn, TOK, HID, HID, 1);

    // GRU
    gemm_nt_kernel<<<dim3(3 * HID / 64, MB), 256>>>(hattn,  gru_wih, gru_bih, nullptr, gi, TOK, 3 * HID, HID, 0);
    gemm_nt_kernel<<<dim3(3 * HID / 64, MB), 256>>>(hidden, gru_whh, gru_bhh, nullptr, gh, TOK, 3 * HID, HID, 0);
    gru_kernel<<<(TOK * HID + 255) / 256, 256>>>(gi, gh, hidden, h_temp_out);

    // decoder
    gemm_nt_kernel<<<dim3(HID / 64, MB), 256>>>(h_temp_out, dec_w1, dec_b1, nullptr, q, TOK, HID, HID, 0);
    ln_gelu_kernel<<<TOK, 256>>>(q, ln2_g, ln2_b, HID);
    gemm_nt_kernel<<<dim3(1, MB), 256>>>(q, dec_w2, dec_b2, nullptr, q_out, TOK, ACT, HID, 0);
}

// round 2
// speedup vs baseline: 2.2098x; 2.2098x over previous
#include <cuda_runtime.h>
#include <math.h>
#include <stdint.h>

// ---------------- problem constants ----------------
#define BB   32
#define NN   512
#define IND  128
#define HID  256
#define HID2 512
#define HEADS 4
#define HD   64
#define ACT  32
#define TOK  (BB*NN)            // 16384 tokens

// ---------------- scratch (device globals; no allocation allowed) --------
__device__ float g_h1[TOK * HID2];      // encoder mid (16384x512)
__device__ float g_hsp[TOK * HID];      // h_spatial
__device__ float g_Wh[TOK * HID];       // GAT per-head projection
__device__ float g_hl[BB * HEADS * NN]; // left scores
__device__ float g_hr[BB * HEADS * NN]; // right scores
__device__ float g_aout[TOK * HID];     // attention output
__device__ float g_hattn[TOK * HID];    // after out-proj + skip
__device__ float g_gi[TOK * 3 * HID];   // GRU input gates
__device__ float g_gh[TOK * 3 * HID];   // GRU hidden gates
__device__ float g_q[TOK * HID];        // decoder mid

// ---------------- tf32 helpers ----------------
__device__ __forceinline__ uint32_t f2tf32(float f) {
    uint32_t r;
    asm("cvt.rna.tf32.f32 %0, %1;" : "=r"(r) : "f"(f));
    return r;
}

__device__ __forceinline__ void mma_tf32(float* d, const uint32_t* a, const uint32_t* b) {
    asm volatile(
        "mma.sync.aligned.m16n8k8.row.col.f32.tf32.tf32.f32 "
        "{%0,%1,%2,%3},{%4,%5,%6,%7},{%8,%9},{%0,%1,%2,%3};"
        : "+f"(d[0]), "+f"(d[1]), "+f"(d[2]), "+f"(d[3])
        : "r"(a[0]), "r"(a[1]), "r"(a[2]), "r"(a[3]),
          "r"(b[0]), "r"(b[1]));
}

// ---------------- TF32 NT GEMM: C[M,N] = A[M,K] @ W[N,K]^T (+b1[n]) (+b2[n]) ---
// BM=128, BN=64, BK=32, 256 threads (8 warps, 4x2), warp tile 32x32 = 2x4 m16n8k8.
// Requirements: M % 128 == 0, K % 32 == 0 (true for all call sites). N guarded.
__global__ void gemm_tf32_kernel(const float* __restrict__ A,
                                 const float* __restrict__ W,
                                 const float* __restrict__ b1,
                                 const float* __restrict__ b2,
                                 float* __restrict__ C,
                                 int M, int N, int K, int accum)
{
    __shared__ uint32_t As[32][132];  // [k][m] tf32 bits
    __shared__ uint32_t Ws[32][68];   // [k][n] tf32 bits

    const int m0 = blockIdx.y * 128;
    const int n0 = blockIdx.x * 64;
    const int tid = threadIdx.x;
    const int w = tid >> 5;
    const int lane = tid & 31;
    const int wm = (w >> 1) * 32;   // warp m origin (0,32,64,96)
    const int wn = (w & 1) * 32;    // warp n origin (0,32)

    float acc[2][4][4];
#pragma unroll
    for (int i = 0; i < 2; i++)
#pragma unroll
        for (int j = 0; j < 4; j++)
#pragma unroll
            for (int r = 0; r < 4; r++) acc[i][j][r] = 0.f;

    const int lk = lane & 3;     // k within fragment
    const int lg = lane >> 2;    // group id (row/col within fragment)

    for (int k0 = 0; k0 < K; k0 += 32) {
        // ---- load A tile: 128x32 floats = 1024 float4, 4 per thread ----
#pragma unroll
        for (int i = 0; i < 4; i++) {
            int f = tid + 256 * i;
            int r = f >> 3;            // 0..127
            int c4 = (f & 7) * 4;      // 0..28
            float4 v = *reinterpret_cast<const float4*>(A + (size_t)(m0 + r) * K + k0 + c4);
            As[c4 + 0][r] = f2tf32(v.x);
            As[c4 + 1][r] = f2tf32(v.y);
            As[c4 + 2][r] = f2tf32(v.z);
            As[c4 + 3][r] = f2tf32(v.w);
        }
        // ---- load W tile: 64x32 floats = 512 float4, 2 per thread ----
#pragma unroll
        for (int i = 0; i < 2; i++) {
            int f = tid + 256 * i;
            int r = f >> 3;            // 0..63
            int c4 = (f & 7) * 4;
            float4 v = make_float4(0.f, 0.f, 0.f, 0.f);
            if (n0 + r < N)
                v = *reinterpret_cast<const float4*>(W + (size_t)(n0 + r) * K + k0 + c4);
            Ws[c4 + 0][r] = f2tf32(v.x);
            Ws[c4 + 1][r] = f2tf32(v.y);
            Ws[c4 + 2][r] = f2tf32(v.z);
            Ws[c4 + 3][r] = f2tf32(v.w);
        }
        __syncthreads();

#pragma unroll
        for (int kk = 0; kk < 4; kk++) {
            const int kb = kk * 8;
            uint32_t af[2][4];
            uint32_t bf[4][2];
#pragma unroll
            for (int im = 0; im < 2; im++) {
                int mr = wm + im * 16 + lg;
                af[im][0] = As[kb + lk][mr];
                af[im][1] = As[kb + lk][mr + 8];
                af[im][2] = As[kb + lk + 4][mr];
                af[im][3] = As[kb + lk + 4][mr + 8];
            }
#pragma unroll
            for (int jn = 0; jn < 4; jn++) {
                int nc = wn + jn * 8 + lg;
                bf[jn][0] = Ws[kb + lk][nc];
                bf[jn][1] = Ws[kb + lk + 4][nc];
            }
#pragma unroll
            for (int im = 0; im < 2; im++)
#pragma unroll
                for (int jn = 0; jn < 4; jn++)
                    mma_tf32(acc[im][jn], af[im], bf[jn]);
        }
        __syncthreads();
    }

    // ---- epilogue ----
#pragma unroll
    for (int im = 0; im < 2; im++) {
#pragma unroll
        for (int jn = 0; jn < 4; jn++) {
            int col0 = n0 + wn + jn * 8 + 2 * lk;
            if (col0 >= N) continue;
            float bias0 = 0.f, bias1 = 0.f;
            if (b1) { bias0 += b1[col0]; bias1 += b1[col0 + 1]; }
            if (b2) { bias0 += b2[col0]; bias1 += b2[col0 + 1]; }
#pragma unroll
            for (int half = 0; half < 2; half++) {
                int row = m0 + wm + im * 16 + lg + half * 8;
                float v0 = acc[im][jn][half * 2 + 0] + bias0;
                float v1 = acc[im][jn][half * 2 + 1] + bias1;
                float2* dst = reinterpret_cast<float2*>(C + (size_t)row * N + col0);
                if (accum) {
                    float2 old = *dst;
                    v0 += old.x; v1 += old.y;
                }
                *dst = make_float2(v0, v1);
            }
        }
    }
}

// ---------------- fused LayerNorm + exact GELU (in place), D = 256 or 512 ----
__device__ __forceinline__ float gelu_exact(float x) {
    return 0.5f * x * (1.0f + erff(x * 0.70710678118654752440f));
}

__global__ void ln_gelu_kernel(float* __restrict__ X,
                               const float* __restrict__ g,
                               const float* __restrict__ b,
                               int D)
{
    __shared__ float red[256];
    float* row = X + (size_t)blockIdx.x * D;
    const int t = threadIdx.x;

    float v0 = row[t];
    float v1 = (D > 256) ? row[t + 256] : 0.f;

    red[t] = v0 + v1;
    __syncthreads();
    for (int o = 128; o; o >>= 1) { if (t < o) red[t] += red[t + o]; __syncthreads(); }
    float mean = red[0] / (float)D;
    __syncthreads();

    float d0 = v0 - mean;
    float d1 = v1 - mean;
    float sq = d0 * d0 + ((D > 256) ? d1 * d1 : 0.f);
    red[t] = sq;
    __syncthreads();
    for (int o = 128; o; o >>= 1) { if (t < o) red[t] += red[t + o]; __syncthreads(); }
    float var = red[0] / (float)D;
    float rstd = rsqrtf(var + 1e-5f);

    row[t] = gelu_exact(d0 * rstd * g[t] + b[t]);
    if (D > 256)
        row[t + 256] = gelu_exact(d1 * rstd * g[t + 256] + b[t + 256]);
}

// ---------------- GAT left/right scores: hl/hr[(b*4+h)*512 + i] --------------
__global__ void lr_kernel(const float* __restrict__ Wh,
                          const float* __restrict__ a,
                          float* __restrict__ hl,
                          float* __restrict__ hr)
{
    const int token = blockIdx.x;             // 0..16383
    const int w = threadIdx.x >> 5;           // 0..7
    const int lane = threadIdx.x & 31;
    const int head = w >> 1;
    const int side = w & 1;

    const float* whp = Wh + (size_t)token * HID + head * HD;
    const float* ap = a + head * (2 * HD) + side * HD;
    float s = whp[lane] * ap[lane] + whp[lane + 32] * ap[lane + 32];
#pragma unroll
    for (int o = 16; o; o >>= 1) s += __shfl_xor_sync(0xffffffffu, s, o);
    if (lane == 0) {
        int bidx = token >> 9;          // /512
        int i = token & 511;
        float* dst = side ? hr : hl;
        dst[((bidx * HEADS + head) << 9) + i] = s;
    }
}

// ---------------- fused GAT masked-softmax + AV ------------------------------
// block = 256 threads = 8 warps, each warp owns one row i of one (b,h);
// warps in a block share the same (b,h) Wh slab -> L1 reuse.
__global__ void gat_attn_kernel(const float* __restrict__ Wh,
                                const float* __restrict__ hl,
                                const float* __restrict__ hr,
                                const int* __restrict__ adj,
                                float* __restrict__ out)
{
    const int blk = blockIdx.x;            // 32*4*64 = 8192
    const int itile = blk & 63;
    const int h = (blk >> 6) & 3;
    const int b = blk >> 8;
    const int w = threadIdx.x >> 5;
    const int lane = threadIdx.x & 31;
    const int i = itile * 8 + w;

    const float l = hl[((b * HEADS + h) << 9) + i];
    const float* rv = hr + ((b * HEADS + h) << 9);
    const int* mrow = adj + ((size_t)b * NN + i) * NN;
    const float* whb = Wh + (size_t)b * NN * HID + h * HD;

    // pass 1: masked row max (leaky-relu applied pre-mask, monotone recompute)
    float mx = -INFINITY;
    for (int j = lane; j < NN; j += 32) {
        if (mrow[j]) {
            float e = l + rv[j];
            e = (e >= 0.f) ? e : 0.2f * e;
            mx = fmaxf(mx, e);
        }
    }
#pragma unroll
    for (int o = 16; o; o >>= 1) mx = fmaxf(mx, __shfl_xor_sync(0xffffffffu, mx, o));

    // pass 2: weights + weighted sum of Wh rows (float2 per lane = 64 cols)
    float s = 0.f;
    float2 acc = make_float2(0.f, 0.f);
    for (int j0 = 0; j0 < NN; j0 += 32) {
        int j = j0 + lane;
        float wgt = 0.f;
        if (mrow[j]) {
            float e = l + rv[j];
            e = (e >= 0.f) ? e : 0.2f * e;
            wgt = expf(e - mx);
        }
        s += wgt;
#pragma unroll
        for (int jj = 0; jj < 32; jj++) {
            float wv = __shfl_sync(0xffffffffu, wgt, jj);
            const float2* wr = reinterpret_cast<const float2*>(whb + (size_t)(j0 + jj) * HID);
            float2 v = wr[lane];
            acc.x += wv * v.x;
            acc.y += wv * v.y;
        }
    }
#pragma unroll
    for (int o = 16; o; o >>= 1) s += __shfl_xor_sync(0xffffffffu, s, o);
    float inv = 1.f / s;

    float2* op = reinterpret_cast<float2*>(out + (size_t)(b * NN + i) * HID + h * HD);
    op[lane] = make_float2(acc.x * inv, acc.y * inv);
}

// ---------------- GRU gates -> h_temp (written straight to output) ----------
__global__ void gru_kernel(const float* __restrict__ gi,
                           const float* __restrict__ gh,
                           const float* __restrict__ hidden,
                           float* __restrict__ h_temp)
{
    int idx = blockIdx.x * blockDim.x + threadIdx.x;   // TOK*HID
    if (idx >= TOK * HID) return;
    int row = idx / HID;
    int c = idx - row * HID;
    const float* gir = gi + (size_t)row * (3 * HID);
    const float* ghr = gh + (size_t)row * (3 * HID);
    float r = 1.f / (1.f + expf(-(gir[c] + ghr[c])));
    float z = 1.f / (1.f + expf(-(gir[HID + c] + ghr[HID + c])));
    float n = tanhf(gir[2 * HID + c] + r * ghr[2 * HID + c]);
    float hprev = hidden[idx];
    h_temp[idx] = (1.f - z) * n + z * hprev;
}

// ---------------- launch ----------------
extern "C" void kernel_launch(void* const* d_in, const int* in_sizes, int n_in,
                              void* d_out, int out_size)
{
    const float* x        = (const float*)d_in[0];
    const int*   adj      = (const int*)  d_in[1];
    const float* hidden   = (const float*)d_in[2];
    const float* enc_w1   = (const float*)d_in[3];
    const float* enc_b1   = (const float*)d_in[4];
    const float* ln1_g    = (const float*)d_in[5];
    const float* ln1_b    = (const float*)d_in[6];
    const float* enc_w2   = (const float*)d_in[7];
    const float* enc_b2   = (const float*)d_in[8];
    const float* pos      = (const float*)d_in[9];
    const float* gat_w    = (const float*)d_in[10];
    const float* gat_b    = (const float*)d_in[11];
    const float* gat_a    = (const float*)d_in[12];
    const float* gat_ow   = (const float*)d_in[13];
    const float* gat_ob   = (const float*)d_in[14];
    const float* skip_w   = (const float*)d_in[15];
    const float* skip_b   = (const float*)d_in[16];
    const float* gru_wih  = (const float*)d_in[17];
    const float* gru_bih  = (const float*)d_in[18];
    const float* gru_whh  = (const float*)d_in[19];
    const float* gru_bhh  = (const float*)d_in[20];
    const float* dec_w1   = (const float*)d_in[21];
    const float* dec_b1   = (const float*)d_in[22];
    const float* ln2_g    = (const float*)d_in[23];
    const float* ln2_b    = (const float*)d_in[24];
    const float* dec_w2   = (const float*)d_in[25];
    const float* dec_b2   = (const float*)d_in[26];

    float* out = (float*)d_out;
    float* q_out = out;                       // (B,N,ACT) = 524288 floats
    float* h_temp_out = out + (size_t)TOK * ACT;  // (B,N,HID)

    float *h1, *hsp, *Wh, *hl, *hr, *aout, *hattn, *gi, *gh, *q;
    cudaGetSymbolAddress((void**)&h1,    g_h1);
    cudaGetSymbolAddress((void**)&hsp,   g_hsp);
    cudaGetSymbolAddress((void**)&Wh,    g_Wh);
    cudaGetSymbolAddress((void**)&hl,    g_hl);
    cudaGetSymbolAddress((void**)&hr,    g_hr);
    cudaGetSymbolAddress((void**)&aout,  g_aout);
    cudaGetSymbolAddress((void**)&hattn, g_hattn);
    cudaGetSymbolAddress((void**)&gi,    g_gi);
    cudaGetSymbolAddress((void**)&gh,    g_gh);
    cudaGetSymbolAddress((void**)&q,     g_q);

    const int MB = TOK / 128;   // 128 row-blocks

    // encoder: Linear(128->512) -> LN -> GELU -> Linear(512->256) + pos
    gemm_tf32_kernel<<<dim3(HID2 / 64, MB), 256>>>(x, enc_w1, enc_b1, nullptr, h1, TOK, HID2, IND, 0);
    ln_gelu_kernel<<<TOK, 256>>>(h1, ln1_g, ln1_b, HID2);
    gemm_tf32_kernel<<<dim3(HID / 64, MB), 256>>>(h1, enc_w2, enc_b2, pos, hsp, TOK, HID, HID2, 0);

    // GAT
    gemm_tf32_kernel<<<dim3(HID / 64, MB), 256>>>(hsp, gat_w, gat_b, nullptr, Wh, TOK, HID, HID, 0);
    lr_kernel<<<TOK, 256>>>(Wh, gat_a, hl, hr);
    gat_attn_kernel<<<BB * HEADS * (NN / 8), 256>>>(Wh, hl, hr, adj, aout);

    // out-proj + skip (accumulated second GEMM)
    gemm_tf32_kernel<<<dim3(HID / 64, MB), 256>>>(aout, gat_ow, gat_ob, skip_b, hattn, TOK, HID, HID, 0);
    gemm_tf32_kernel<<<dim3(HID / 64, MB), 256>>>(hsp, skip_w, nullptr, nullptr, hattn, TOK, HID, HID, 1);

    // GRU
    gemm_tf32_kernel<<<dim3(3 * HID / 64, MB), 256>>>(hattn,  gru_wih, gru_bih, nullptr, gi, TOK, 3 * HID, HID, 0);
    gemm_tf32_kernel<<<dim3(3 * HID / 64, MB), 256>>>(hidden, gru_whh, gru_bhh, nullptr, gh, TOK, 3 * HID, HID, 0);
    gru_kernel<<<(TOK * HID + 255) / 256, 256>>>(gi, gh, hidden, h_temp_out);

    // decoder
    gemm_tf32_kernel<<<dim3(HID / 64, MB), 256>>>(h_temp_out, dec_w1, dec_b1, nullptr, q, TOK, HID, HID, 0);
    ln_gelu_kernel<<<TOK, 256>>>(q, ln2_g, ln2_b, HID);
    gemm_tf32_kernel<<<dim3(1, MB), 256>>>(q, dec_w2, dec_b2, nullptr, q_out, TOK, ACT, HID, 0);
}

// round 3
// speedup vs baseline: 3.0179x; 1.3657x over previous
#include <cuda_runtime.h>
#include <math.h>
#include <stdint.h>

// ---------------- problem constants ----------------
#define BB   32
#define NN   512
#define IND  128
#define HID  256
#define HID2 512
#define HEADS 4
#define HD   64
#define ACT  32
#define TOK  (BB*NN)            // 16384 tokens

// ---------------- scratch (device globals) --------
__device__ float g_h1[TOK * HID2];
__device__ float g_hsp[TOK * HID];
__device__ float g_Wh[TOK * HID];
__device__ float g_hl[BB * HEADS * NN];
__device__ float g_hr[BB * HEADS * NN];
__device__ float g_aout[TOK * HID];
__device__ float g_hattn[TOK * HID];
__device__ float g_gi[TOK * 3 * HID];
__device__ float g_gh[TOK * 3 * HID];
__device__ float g_q[TOK * HID];
__device__ uint32_t g_mbits[(size_t)BB * NN * (NN / 32)];   // packed adj, 1MB

// ---------------- tf32 helpers ----------------
__device__ __forceinline__ uint32_t f2tf32(float f) {
    uint32_t r;
    asm("cvt.rna.tf32.f32 %0, %1;" : "=r"(r) : "f"(f));
    return r;
}

__device__ __forceinline__ void mma_tf32(float* d, const uint32_t* a, const uint32_t* b) {
    asm volatile(
        "mma.sync.aligned.m16n8k8.row.col.f32.tf32.tf32.f32 "
        "{%0,%1,%2,%3},{%4,%5,%6,%7},{%8,%9},{%0,%1,%2,%3};"
        : "+f"(d[0]), "+f"(d[1]), "+f"(d[2]), "+f"(d[3])
        : "r"(a[0]), "r"(a[1]), "r"(a[2]), "r"(a[3]),
          "r"(b[0]), "r"(b[1]));
}

// ---------------- TF32 NT GEMM with fragment-packed smem --------------------
// C[M,N] = A[M,K] @ W[N,K]^T (+b1) (+b2). BM=128, BN=64, BK=32, 256 thr.
// Smem tiles stored directly in mma fragment order:
//   Afr[kk][m16][lane] = uint4 {a0,a1,a2,a3},  Bfr[kk][n8][lane] = uint2 {b0,b1}
__global__ void gemm_tf32_kernel(const float* __restrict__ A,
                                 const float* __restrict__ W,
                                 const float* __restrict__ b1,
                                 const float* __restrict__ b2,
                                 float* __restrict__ C,
                                 int M, int N, int K, int accum)
{
    __shared__ uint4 Afr[4 * 8 * 32];   // 16KB
    __shared__ uint2 Bfr[4 * 8 * 32];   // 8KB

    const int m0 = blockIdx.y * 128;
    const int n0 = blockIdx.x * 64;
    const int tid = threadIdx.x;
    const int w = tid >> 5;
    const int lane = tid & 31;
    const int wm16 = (w >> 1) * 2;   // m16-tile base (0,2,4,6)
    const int wn8 = (w & 1) * 4;     // n8-tile base (0,4)

    float acc[2][4][4];
#pragma unroll
    for (int i = 0; i < 2; i++)
#pragma unroll
        for (int j = 0; j < 4; j++)
#pragma unroll
            for (int r = 0; r < 4; r++) acc[i][j][r] = 0.f;

    uint32_t* Afw = reinterpret_cast<uint32_t*>(Afr);
    uint32_t* Bfw = reinterpret_cast<uint32_t*>(Bfr);

    for (int k0 = 0; k0 < K; k0 += 32) {
        // ---- A tile 128x32: 4 float4 per thread, store into fragment slots ----
#pragma unroll
        for (int i = 0; i < 4; i++) {
            int f = tid + 256 * i;
            int r = f >> 3;            // 0..127
            int c4 = (f & 7) * 4;      // 0..28
            float4 v = *reinterpret_cast<const float4*>(A + (size_t)(m0 + r) * K + k0 + c4);
            int kk = c4 >> 3;
            int kh = (c4 >> 2) & 1;
            int ri = kh * 2 + ((r >> 3) & 1);
            int base = (((kk * 8 + (r >> 4)) * 32) + (r & 7) * 4) * 4 + ri;
            Afw[base + 0]  = f2tf32(v.x);
            Afw[base + 4]  = f2tf32(v.y);
            Afw[base + 8]  = f2tf32(v.z);
            Afw[base + 12] = f2tf32(v.w);
        }
        // ---- W tile 64x32: 2 float4 per thread ----
#pragma unroll
        for (int i = 0; i < 2; i++) {
            int f = tid + 256 * i;
            int r = f >> 3;            // 0..63 (n)
            int c4 = (f & 7) * 4;
            float4 v = make_float4(0.f, 0.f, 0.f, 0.f);
            if (n0 + r < N)
                v = *reinterpret_cast<const float4*>(W + (size_t)(n0 + r) * K + k0 + c4);
            int kk = c4 >> 3;
            int kh = (c4 >> 2) & 1;
            int base = (((kk * 8 + (r >> 3)) * 32) + (r & 7) * 4) * 2 + kh;
            Bfw[base + 0] = f2tf32(v.x);
            Bfw[base + 2] = f2tf32(v.y);
            Bfw[base + 4] = f2tf32(v.z);
            Bfw[base + 6] = f2tf32(v.w);
        }
        __syncthreads();

#pragma unroll
        for (int kk = 0; kk < 4; kk++) {
            uint4 av[2];
            uint2 bv[4];
#pragma unroll
            for (int im = 0; im < 2; im++)
                av[im] = Afr[(kk * 8 + wm16 + im) * 32 + lane];
#pragma unroll
            for (int jn = 0; jn < 4; jn++)
                bv[jn] = Bfr[(kk * 8 + wn8 + jn) * 32 + lane];
#pragma unroll
            for (int im = 0; im < 2; im++)
#pragma unroll
                for (int jn = 0; jn < 4; jn++)
                    mma_tf32(acc[im][jn],
                             reinterpret_cast<const uint32_t*>(&av[im]),
                             reinterpret_cast<const uint32_t*>(&bv[jn]));
        }
        __syncthreads();
    }

    // ---- epilogue ----
    const int lg = lane >> 2;
    const int lk = lane & 3;
#pragma unroll
    for (int im = 0; im < 2; im++) {
#pragma unroll
        for (int jn = 0; jn < 4; jn++) {
            int col0 = n0 + (w & 1) * 32 + jn * 8 + 2 * lk;
            if (col0 >= N) continue;
            float bias0 = 0.f, bias1 = 0.f;
            if (b1) { bias0 += b1[col0]; bias1 += b1[col0 + 1]; }
            if (b2) { bias0 += b2[col0]; bias1 += b2[col0 + 1]; }
#pragma unroll
            for (int half = 0; half < 2; half++) {
                int row = m0 + (w >> 1) * 32 + im * 16 + lg + half * 8;
                float v0 = acc[im][jn][half * 2 + 0] + bias0;
                float v1 = acc[im][jn][half * 2 + 1] + bias1;
                float2* dst = reinterpret_cast<float2*>(C + (size_t)row * N + col0);
                if (accum) {
                    float2 old = *dst;
                    v0 += old.x; v1 += old.y;
                }
                *dst = make_float2(v0, v1);
            }
        }
    }
}

// ---------------- fused LayerNorm + exact GELU (in place) ----
__device__ __forceinline__ float gelu_exact(float x) {
    return 0.5f * x * (1.0f + erff(x * 0.70710678118654752440f));
}

__global__ void ln_gelu_kernel(float* __restrict__ X,
                               const float* __restrict__ g,
                               const float* __restrict__ b,
                               int D)
{
    __shared__ float red[256];
    float* row = X + (size_t)blockIdx.x * D;
    const int t = threadIdx.x;

    float v0 = row[t];
    float v1 = (D > 256) ? row[t + 256] : 0.f;

    red[t] = v0 + v1;
    __syncthreads();
    for (int o = 128; o; o >>= 1) { if (t < o) red[t] += red[t + o]; __syncthreads(); }
    float mean = red[0] / (float)D;
    __syncthreads();

    float d0 = v0 - mean;
    float d1 = v1 - mean;
    float sq = d0 * d0 + ((D > 256) ? d1 * d1 : 0.f);
    red[t] = sq;
    __syncthreads();
    for (int o = 128; o; o >>= 1) { if (t < o) red[t] += red[t + o]; __syncthreads(); }
    float var = red[0] / (float)D;
    float rstd = rsqrtf(var + 1e-5f);

    row[t] = gelu_exact(d0 * rstd * g[t] + b[t]);
    if (D > 256)
        row[t + 256] = gelu_exact(d1 * rstd * g[t + 256] + b[t + 256]);
}

// ---------------- pack adjacency into bitmasks ------------------------------
__global__ void pack_adj_kernel(const int* __restrict__ adj, uint32_t* __restrict__ mb)
{
    int row = blockIdx.x;                       // 0..B*N-1
    int t = threadIdx.x;                        // 0..511
    int v = adj[(size_t)row * NN + t];
    unsigned bal = __ballot_sync(0xffffffffu, v != 0);
    if ((t & 31) == 0) mb[row * (NN / 32) + (t >> 5)] = bal;
}

// ---------------- GAT left/right scores -------------------------------------
__global__ void lr_kernel(const float* __restrict__ Wh,
                          const float* __restrict__ a,
                          float* __restrict__ hl,
                          float* __restrict__ hr)
{
    const int token = blockIdx.x;
    const int w = threadIdx.x >> 5;
    const int lane = threadIdx.x & 31;
    const int head = w >> 1;
    const int side = w & 1;

    const float* whp = Wh + (size_t)token * HID + head * HD;
    const float* ap = a + head * (2 * HD) + side * HD;
    float s = whp[lane] * ap[lane] + whp[lane + 32] * ap[lane + 32];
#pragma unroll
    for (int o = 16; o; o >>= 1) s += __shfl_xor_sync(0xffffffffu, s, o);
    if (lane == 0) {
        int bidx = token >> 9;
        int i = token & 511;
        float* dst = side ? hr : hl;
        dst[((bidx * HEADS + head) << 9) + i] = s;
    }
}

// ---------------- GAT attention: exp-factorized + tf32 MMA ------------------
// grid = itile(4) x h(4) x b(32) flat; block = 256 threads (8 warps).
// Per block: output rows i0..i0+127 of (b,h), full K=512 reduction.
// Weight: w_ij = mask * (cond ? exp(l-Lmax)*exp(r-Rmax) : exp(.2l-C)*exp(.2r)),
// cond = (l+r>=0), C = Lmax+Rmax. Softmax shift cancels in num/den.
__global__ void gat_attn_mma_kernel(const float* __restrict__ Wh,
                                    const float* __restrict__ hl,
                                    const float* __restrict__ hr,
                                    const uint32_t* __restrict__ mb,
                                    float* __restrict__ out)
{
    __shared__ float4 sJF[NN];            // {r_j, E1_j, E2_j, 0}  8KB
    __shared__ float sA1[128], sA2[128], sNL[128];
    __shared__ uint4 sP[4 * 8 * 32];      // P fragments 16KB
    __shared__ uint32_t sW[32][68];       // Wh tile (tf32 bits), padded
    __shared__ float sS[128];
    __shared__ float sRed[16];
    __shared__ float sMax[2];

    const int bx = blockIdx.x;
    const int it = bx & 3;
    const int h = (bx >> 2) & 3;
    const int b = bx >> 4;
    const int tid = threadIdx.x;
    const int w = tid >> 5;
    const int lane = tid & 31;
    const int lg = lane >> 2;
    const int lk = lane & 3;
    const int bh = b * HEADS + h;
    const int i0 = it * 128;

    // ---- load l (block rows) and r (all 512), reduce maxes ----
    float lv = 0.f;
    if (tid < 128) lv = hl[(bh << 9) + i0 + tid];
    float rv0 = hr[(bh << 9) + tid];
    float rv1 = hr[(bh << 9) + 256 + tid];

    float lm = (tid < 128) ? lv : -INFINITY;
    float rm = fmaxf(rv0, rv1);
#pragma unroll
    for (int o = 16; o; o >>= 1) {
        lm = fmaxf(lm, __shfl_xor_sync(0xffffffffu, lm, o));
        rm = fmaxf(rm, __shfl_xor_sync(0xffffffffu, rm, o));
    }
    if (lane == 0) { sRed[w] = lm; sRed[8 + w] = rm; }
    __syncthreads();
    if (tid == 0) {
        float L = -INFINITY, R = -INFINITY;
#pragma unroll
        for (int q = 0; q < 8; q++) { L = fmaxf(L, sRed[q]); R = fmaxf(R, sRed[8 + q]); }
        sMax[0] = L; sMax[1] = R;
    }
    __syncthreads();
    const float Lmax = sMax[0], Rmax = sMax[1];
    const float C1 = Lmax + Rmax;

    sJF[tid]       = make_float4(rv0, expf(rv0 - Rmax), expf(0.2f * rv0), 0.f);
    sJF[tid + 256] = make_float4(rv1, expf(rv1 - Rmax), expf(0.2f * rv1), 0.f);
    if (tid < 128) {
        sA1[tid] = expf(lv - Lmax);
        sA2[tid] = expf(0.2f * lv - C1);
        sNL[tid] = -lv;
    }
    __syncthreads();

    // P-build roles: this thread owns rows r0 = w*16+lg, r1 = r0+8; cols lk, lk+4 per kk
    const int r0 = w * 16 + lg;
    const int r1 = r0 + 8;
    const float A1a = sA1[r0], A2a = sA2[r0], NLa = sNL[r0];
    const float A1b = sA1[r1], A2b = sA2[r1], NLb = sNL[r1];
    const uint32_t* mrow0 = mb + ((size_t)(b << 9) + i0 + r0) * (NN / 32);
    const uint32_t* mrow1 = mb + ((size_t)(b << 9) + i0 + r1) * (NN / 32);
    float psum0 = 0.f, psum1 = 0.f;

    // MMA roles
    const int wm16 = (w >> 1) * 2;
    const int wn = (w & 1) * 32;
    float acc[2][4][4];
#pragma unroll
    for (int i = 0; i < 2; i++)
#pragma unroll
        for (int j = 0; j < 4; j++)
#pragma unroll
            for (int r = 0; r < 4; r++) acc[i][j][r] = 0.f;

    const float* whbase = Wh + (size_t)b * NN * HID + h * HD;

    for (int jt = 0; jt < 16; jt++) {
        // ---- stage Wh tile [32 j' x 64 d] as tf32 bits ----
#pragma unroll
        for (int itr = 0; itr < 2; itr++) {
            int f = tid + 256 * itr;
            int jp = f >> 4;
            int dq = (f & 15) * 4;
            float4 v = *reinterpret_cast<const float4*>(whbase + (size_t)(jt * 32 + jp) * HID + dq);
            sW[jp][dq + 0] = f2tf32(v.x);
            sW[jp][dq + 1] = f2tf32(v.y);
            sW[jp][dq + 2] = f2tf32(v.z);
            sW[jp][dq + 3] = f2tf32(v.w);
        }
        // ---- build P fragments ----
        uint32_t mw0 = mrow0[jt];
        uint32_t mw1 = mrow1[jt];
#pragma unroll
        for (int kk = 0; kk < 4; kk++) {
            int c0 = kk * 8 + lk;
            int c1 = c0 + 4;
            float4 jf0 = sJF[jt * 32 + c0];
            float4 jf1 = sJF[jt * 32 + c1];
            bool cd00 = (jf0.x >= NLa), cd10 = (jf0.x >= NLb);
            bool cd01 = (jf1.x >= NLa), cd11 = (jf1.x >= NLb);
            float p00 = ((mw0 >> c0) & 1) ? (cd00 ? A1a * jf0.y : A2a * jf0.z) : 0.f;
            float p10 = ((mw1 >> c0) & 1) ? (cd10 ? A1b * jf0.y : A2b * jf0.z) : 0.f;
            float p01 = ((mw0 >> c1) & 1) ? (cd01 ? A1a * jf1.y : A2a * jf1.z) : 0.f;
            float p11 = ((mw1 >> c1) & 1) ? (cd11 ? A1b * jf1.y : A2b * jf1.z) : 0.f;
            psum0 += p00 + p01;
            psum1 += p10 + p11;
            uint4 pk;
            pk.x = f2tf32(p00);   // ri0: (khalf0,row r0)
            pk.y = f2tf32(p10);   // ri1: (khalf0,row r1)
            pk.z = f2tf32(p01);   // ri2: (khalf1,row r0)
            pk.w = f2tf32(p11);   // ri3: (khalf1,row r1)
            sP[(kk * 8 + w) * 32 + lane] = pk;
        }
        __syncthreads();

        // ---- MMA: acc += P_tile @ Wh_tile ----
#pragma unroll
        for (int kk = 0; kk < 4; kk++) {
            uint4 av[2];
#pragma unroll
            for (int im = 0; im < 2; im++)
                av[im] = sP[(kk * 8 + wm16 + im) * 32 + lane];
#pragma unroll
            for (int jn = 0; jn < 4; jn++) {
                int nc = wn + jn * 8 + lg;
                uint32_t bf[2];
                bf[0] = sW[kk * 8 + lk][nc];
                bf[1] = sW[kk * 8 + 4 + lk][nc];
#pragma unroll
                for (int im = 0; im < 2; im++)
                    mma_tf32(acc[im][jn],
                             reinterpret_cast<const uint32_t*>(&av[im]), bf);
            }
        }
        __syncthreads();
    }

    // ---- row sums: reduce over the 4 lanes (lk) sharing each row ----
    psum0 += __shfl_xor_sync(0xffffffffu, psum0, 1);
    psum0 += __shfl_xor_sync(0xffffffffu, psum0, 2);
    psum1 += __shfl_xor_sync(0xffffffffu, psum1, 1);
    psum1 += __shfl_xor_sync(0xffffffffu, psum1, 2);
    if (lk == 0) { sS[r0] = psum0; sS[r1] = psum1; }
    __syncthreads();

    // ---- epilogue: normalize and store ----
#pragma unroll
    for (int im = 0; im < 2; im++) {
#pragma unroll
        for (int half = 0; half < 2; half++) {
            int rloc = (w >> 1) * 32 + im * 16 + lg + half * 8;
            float inv = 1.f / sS[rloc];
            int grow = (b << 9) + i0 + rloc;
#pragma unroll
            for (int jn = 0; jn < 4; jn++) {
                int col = wn + jn * 8 + 2 * lk;
                float2* dst = reinterpret_cast<float2*>(out + (size_t)grow * HID + h * HD + col);
                *dst = make_float2(acc[im][jn][half * 2 + 0] * inv,
                                   acc[im][jn][half * 2 + 1] * inv);
            }
        }
    }
}

// ---------------- GRU gates -> h_temp ----------
__global__ void gru_kernel(const float* __restrict__ gi,
                           const float* __restrict__ gh,
                           const float* __restrict__ hidden,
                           float* __restrict__ h_temp)
{
    int idx = blockIdx.x * blockDim.x + threadIdx.x;
    if (idx >= TOK * HID) return;
    int row = idx / HID;
    int c = idx - row * HID;
    const float* gir = gi + (size_t)row * (3 * HID);
    const float* ghr = gh + (size_t)row * (3 * HID);
    float r = 1.f / (1.f + expf(-(gir[c] + ghr[c])));
    float z = 1.f / (1.f + expf(-(gir[HID + c] + ghr[HID + c])));
    float n = tanhf(gir[2 * HID + c] + r * ghr[2 * HID + c]);
    float hprev = hidden[idx];
    h_temp[idx] = (1.f - z) * n + z * hprev;
}

// ---------------- launch ----------------
extern "C" void kernel_launch(void* const* d_in, const int* in_sizes, int n_in,
                              void* d_out, int out_size)
{
    const float* x        = (const float*)d_in[0];
    const int*   adj      = (const int*)  d_in[1];
    const float* hidden   = (const float*)d_in[2];
    const float* enc_w1   = (const float*)d_in[3];
    const float* enc_b1   = (const float*)d_in[4];
    const float* ln1_g    = (const float*)d_in[5];
    const float* ln1_b    = (const float*)d_in[6];
    const float* enc_w2   = (const float*)d_in[7];
    const float* enc_b2   = (const float*)d_in[8];
    const float* pos      = (const float*)d_in[9];
    const float* gat_w    = (const float*)d_in[10];
    const float* gat_b    = (const float*)d_in[11];
    const float* gat_a    = (const float*)d_in[12];
    const float* gat_ow   = (const float*)d_in[13];
    const float* gat_ob   = (const float*)d_in[14];
    const float* skip_w   = (const float*)d_in[15];
    const float* skip_b   = (const float*)d_in[16];
    const float* gru_wih  = (const float*)d_in[17];
    const float* gru_bih  = (const float*)d_in[18];
    const float* gru_whh  = (const float*)d_in[19];
    const float* gru_bhh  = (const float*)d_in[20];
    const float* dec_w1   = (const float*)d_in[21];
    const float* dec_b1   = (const float*)d_in[22];
    const float* ln2_g    = (const float*)d_in[23];
    const float* ln2_b    = (const float*)d_in[24];
    const float* dec_w2   = (const float*)d_in[25];
    const float* dec_b2   = (const float*)d_in[26];

    float* out = (float*)d_out;
    float* q_out = out;
    float* h_temp_out = out + (size_t)TOK * ACT;

    float *h1, *hsp, *Wh, *hl, *hr, *aout, *hattn, *gi, *gh, *q;
    uint32_t* mbits;
    cudaGetSymbolAddress((void**)&h1,    g_h1);
    cudaGetSymbolAddress((void**)&hsp,   g_hsp);
    cudaGetSymbolAddress((void**)&Wh,    g_Wh);
    cudaGetSymbolAddress((void**)&hl,    g_hl);
    cudaGetSymbolAddress((void**)&hr,    g_hr);
    cudaGetSymbolAddress((void**)&aout,  g_aout);
    cudaGetSymbolAddress((void**)&hattn, g_hattn);
    cudaGetSymbolAddress((void**)&gi,    g_gi);
    cudaGetSymbolAddress((void**)&gh,    g_gh);
    cudaGetSymbolAddress((void**)&q,     g_q);
    cudaGetSymbolAddress((void**)&mbits, g_mbits);

    const int MB = TOK / 128;

    // pack adjacency (independent of everything else; do it first)
    pack_adj_kernel<<<TOK, 512>>>(adj, mbits);

    // encoder
    gemm_tf32_kernel<<<dim3(HID2 / 64, MB), 256>>>(x, enc_w1, enc_b1, nullptr, h1, TOK, HID2, IND, 0);
    ln_gelu_kernel<<<TOK, 256>>>(h1, ln1_g, ln1_b, HID2);
    gemm_tf32_kernel<<<dim3(HID / 64, MB), 256>>>(h1, enc_w2, enc_b2, pos, hsp, TOK, HID, HID2, 0);

    // GAT
    gemm_tf32_kernel<<<dim3(HID / 64, MB), 256>>>(hsp, gat_w, gat_b, nullptr, Wh, TOK, HID, HID, 0);
    lr_kernel<<<TOK, 256>>>(Wh, gat_a, hl, hr);
    gat_attn_mma_kernel<<<BB * HEADS * 4, 256>>>(Wh, hl, hr, mbits, aout);

    // out-proj + skip
    gemm_tf32_kernel<<<dim3(HID / 64, MB), 256>>>(aout, gat_ow, gat_ob, skip_b, hattn, TOK, HID, HID, 0);
    gemm_tf32_kernel<<<dim3(HID / 64, MB), 256>>>(hsp, skip_w, nullptr, nullptr, hattn, TOK, HID, HID, 1);

    // GRU
    gemm_tf32_kernel<<<dim3(3 * HID / 64, MB), 256>>>(hattn,  gru_wih, gru_bih, nullptr, gi, TOK, 3 * HID, HID, 0);
    gemm_tf32_kernel<<<dim3(3 * HID / 64, MB), 256>>>(hidden, gru_whh, gru_bhh, nullptr, gh, TOK, 3 * HID, HID, 0);
    gru_kernel<<<(TOK * HID + 255) / 256, 256>>>(gi, gh, hidden, h_temp_out);

    // decoder
    gemm_tf32_kernel<<<dim3(HID / 64, MB), 256>>>(h_temp_out, dec_w1, dec_b1, nullptr, q, TOK, HID, HID, 0);
    ln_gelu_kernel<<<TOK, 256>>>(q, ln2_g, ln2_b, HID);
    gemm_tf32_kernel<<<dim3(1, MB), 256>>>(q, dec_w2, dec_b2, nullptr, q_out, TOK, ACT, HID, 0);
}

// round 4
// speedup vs baseline: 4.5409x; 1.5047x over previous
#include <cuda_runtime.h>
#include <math.h>
#include <stdint.h>

// ---------------- problem constants ----------------
#define BB   32
#define NN   512
#define IND  128
#define HID  256
#define HID2 512
#define HEADS 4
#define HD   64
#define ACT  32
#define TOK  (BB*NN)            // 16384 tokens

// GEMM smem geometry
#define AST  36                 // row stride (32 k + 4 pad), 144B, 16B-aligned
#define A_WORDS (128 * AST)
#define W_WORDS (64 * AST)
#define GEMM_SMEM_BYTES ((2 * A_WORDS + 2 * W_WORDS) * 4)   // 55296

// ---------------- scratch (device globals) --------
__device__ float g_h1[TOK * HID2];
__device__ float g_hsp[TOK * HID];
__device__ float g_Wh[TOK * HID];
__device__ float g_hl[BB * HEADS * NN];
__device__ float g_hr[BB * HEADS * NN];
__device__ float g_aout[TOK * HID];
__device__ float g_hattn[TOK * HID];
__device__ float g_gi[TOK * 3 * HID];
__device__ float g_gh[TOK * 3 * HID];
__device__ float g_q[TOK * HID];
__device__ uint32_t g_mbits[(size_t)BB * NN * (NN / 32)];   // packed adj, 1MB

// ---------------- tf32 helpers ----------------
__device__ __forceinline__ uint32_t f2tf32(float f) {
    uint32_t r;
    asm("cvt.rna.tf32.f32 %0, %1;" : "=r"(r) : "f"(f));
    return r;
}

__device__ __forceinline__ void mma_tf32(float* d, const uint32_t* a, const uint32_t* b) {
    asm volatile(
        "mma.sync.aligned.m16n8k8.row.col.f32.tf32.tf32.f32 "
        "{%0,%1,%2,%3},{%4,%5,%6,%7},{%8,%9},{%0,%1,%2,%3};"
        : "+f"(d[0]), "+f"(d[1]), "+f"(d[2]), "+f"(d[3])
        : "r"(a[0]), "r"(a[1]), "r"(a[2]), "r"(a[3]),
          "r"(b[0]), "r"(b[1]));
}

// ---------------- TF32 NT GEMM, double-buffered reg-staged pipeline ---------
// C[M,N] = A[M,K] @ W[N,K]^T (+b1) (+b2). BM=128, BN=64, BK=32, 256 thr.
// Smem [m][k] stride-36: STS.128 stores conflict-free, LDS.32 frag loads
// conflict-free (bank = 4*lg + lk).
__global__ void __launch_bounds__(256, 3)
gemm_tf32_kernel(const float* __restrict__ A,
                 const float* __restrict__ W,
                 const float* __restrict__ b1,
                 const float* __restrict__ b2,
                 float* __restrict__ C,
                 int M, int N, int K, int accum)
{
    extern __shared__ uint32_t smem[];
    uint32_t* Asm = smem;                    // 2 bufs of A_WORDS
    uint32_t* Wsm = smem + 2 * A_WORDS;      // 2 bufs of W_WORDS

    const int m0 = blockIdx.y * 128;
    const int n0 = blockIdx.x * 64;
    const int tid = threadIdx.x;
    const int w = tid >> 5;
    const int lane = tid & 31;
    const int lg = lane >> 2;
    const int lk = lane & 3;
    const int wm = (w >> 1) * 32;
    const int wn = (w & 1) * 32;

    float acc[2][4][4];
#pragma unroll
    for (int i = 0; i < 2; i++)
#pragma unroll
        for (int j = 0; j < 4; j++)
#pragma unroll
            for (int r = 0; r < 4; r++) acc[i][j][r] = 0.f;

    const int ar = tid >> 3;            // A: row 0..127 (tid-based part)
    const int ac4 = (tid & 7) * 4;      // k offset 0..28
    const int nt = K >> 5;

    float4 aReg[4];
    float4 wReg[2];

    // ---- prologue: stage tile 0 ----
#pragma unroll
    for (int i = 0; i < 4; i++)
        aReg[i] = *reinterpret_cast<const float4*>(A + (size_t)(m0 + ar + 32 * i) * K + ac4);
#pragma unroll
    for (int i = 0; i < 2; i++) {
        int r = ar + 32 * i;            // 0..63 valid for i<2 since ar<32? no: ar 0..31 for i.. 
        // (ar ranges 0..31 only for tid<256/8=32.. fix below)
        wReg[i] = make_float4(0.f, 0.f, 0.f, 0.f);
        (void)r;
    }
    // W rows: 64 rows x 8 quads = 512 quads, 2 per thread: rows tid>>3 and 32+(tid>>3)? tid>>3 is 0..31.
    {
        int r0 = tid >> 3;              // 0..31
#pragma unroll
        for (int i = 0; i < 2; i++) {
            int r = r0 + 32 * i;        // 0..63
            if (n0 + r < N)
                wReg[i] = *reinterpret_cast<const float4*>(W + (size_t)(n0 + r) * K + ac4);
            else
                wReg[i] = make_float4(0.f, 0.f, 0.f, 0.f);
        }
    }

    for (int t = 0; t < nt; t++) {
        uint32_t* Ab = Asm + (t & 1) * A_WORDS;
        uint32_t* Wb = Wsm + (t & 1) * W_WORDS;

        // ---- STS staged regs (STS.128, conflict-free) ----
#pragma unroll
        for (int i = 0; i < 4; i++) {
            uint4 pv;
            pv.x = f2tf32(aReg[i].x); pv.y = f2tf32(aReg[i].y);
            pv.z = f2tf32(aReg[i].z); pv.w = f2tf32(aReg[i].w);
            *reinterpret_cast<uint4*>(&Ab[(ar + 32 * i) * AST + ac4]) = pv;
        }
        {
            int r0 = tid >> 3;
#pragma unroll
            for (int i = 0; i < 2; i++) {
                uint4 pv;
                pv.x = f2tf32(wReg[i].x); pv.y = f2tf32(wReg[i].y);
                pv.z = f2tf32(wReg[i].z); pv.w = f2tf32(wReg[i].w);
                *reinterpret_cast<uint4*>(&Wb[(r0 + 32 * i) * AST + ac4]) = pv;
            }
        }

        // ---- prefetch next tile into regs ----
        if (t + 1 < nt) {
            int kof = (t + 1) * 32 + ac4;
#pragma unroll
            for (int i = 0; i < 4; i++)
                aReg[i] = *reinterpret_cast<const float4*>(A + (size_t)(m0 + ar + 32 * i) * K + kof);
            int r0 = tid >> 3;
#pragma unroll
            for (int i = 0; i < 2; i++) {
                int r = r0 + 32 * i;
                if (n0 + r < N)
                    wReg[i] = *reinterpret_cast<const float4*>(W + (size_t)(n0 + r) * K + kof);
                else
                    wReg[i] = make_float4(0.f, 0.f, 0.f, 0.f);
            }
        }

        __syncthreads();

        // ---- 4 k-octets of MMAs ----
#pragma unroll
        for (int kk = 0; kk < 4; kk++) {
            const int kb = kk * 8;
            uint32_t af[2][4];
            uint32_t bf[4][2];
#pragma unroll
            for (int im = 0; im < 2; im++) {
                int mr = wm + im * 16 + lg;
                af[im][0] = Ab[mr * AST + kb + lk];
                af[im][1] = Ab[(mr + 8) * AST + kb + lk];
                af[im][2] = Ab[mr * AST + kb + lk + 4];
                af[im][3] = Ab[(mr + 8) * AST + kb + lk + 4];
            }
#pragma unroll
            for (int jn = 0; jn < 4; jn++) {
                int nc = wn + jn * 8 + lg;
                bf[jn][0] = Wb[nc * AST + kb + lk];
                bf[jn][1] = Wb[nc * AST + kb + lk + 4];
            }
#pragma unroll
            for (int im = 0; im < 2; im++)
#pragma unroll
                for (int jn = 0; jn < 4; jn++)
                    mma_tf32(acc[im][jn], af[im], bf[jn]);
        }
        // no trailing sync: next STS targets the other buffer; barrier above
        // guarantees MMAs two tiles back are complete before buffer reuse.
    }

    // ---- epilogue ----
#pragma unroll
    for (int im = 0; im < 2; im++) {
#pragma unroll
        for (int jn = 0; jn < 4; jn++) {
            int col0 = n0 + wn + jn * 8 + 2 * lk;
            if (col0 >= N) continue;
            float bias0 = 0.f, bias1 = 0.f;
            if (b1) { bias0 += b1[col0]; bias1 += b1[col0 + 1]; }
            if (b2) { bias0 += b2[col0]; bias1 += b2[col0 + 1]; }
#pragma unroll
            for (int half = 0; half < 2; half++) {
                int row = m0 + wm + im * 16 + lg + half * 8;
                float v0 = acc[im][jn][half * 2 + 0] + bias0;
                float v1 = acc[im][jn][half * 2 + 1] + bias1;
                float2* dst = reinterpret_cast<float2*>(C + (size_t)row * N + col0);
                if (accum) {
                    float2 old = *dst;
                    v0 += old.x; v1 += old.y;
                }
                *dst = make_float2(v0, v1);
            }
        }
    }
}

// ---------------- fused LayerNorm + exact GELU (in place) ----
__device__ __forceinline__ float gelu_exact(float x) {
    return 0.5f * x * (1.0f + erff(x * 0.70710678118654752440f));
}

__global__ void ln_gelu_kernel(float* __restrict__ X,
                               const float* __restrict__ g,
                               const float* __restrict__ b,
                               int D)
{
    __shared__ float red[256];
    float* row = X + (size_t)blockIdx.x * D;
    const int t = threadIdx.x;

    float v0 = row[t];
    float v1 = (D > 256) ? row[t + 256] : 0.f;

    red[t] = v0 + v1;
    __syncthreads();
    for (int o = 128; o; o >>= 1) { if (t < o) red[t] += red[t + o]; __syncthreads(); }
    float mean = red[0] / (float)D;
    __syncthreads();

    float d0 = v0 - mean;
    float d1 = v1 - mean;
    float sq = d0 * d0 + ((D > 256) ? d1 * d1 : 0.f);
    red[t] = sq;
    __syncthreads();
    for (int o = 128; o; o >>= 1) { if (t < o) red[t] += red[t + o]; __syncthreads(); }
    float var = red[0] / (float)D;
    float rstd = rsqrtf(var + 1e-5f);

    row[t] = gelu_exact(d0 * rstd * g[t] + b[t]);
    if (D > 256)
        row[t + 256] = gelu_exact(d1 * rstd * g[t + 256] + b[t + 256]);
}

// ---------------- pack adjacency into bitmasks ------------------------------
__global__ void pack_adj_kernel(const int* __restrict__ adj, uint32_t* __restrict__ mb)
{
    int row = blockIdx.x;
    int t = threadIdx.x;
    int v = adj[(size_t)row * NN + t];
    unsigned bal = __ballot_sync(0xffffffffu, v != 0);
    if ((t & 31) == 0) mb[row * (NN / 32) + (t >> 5)] = bal;
}

// ---------------- GAT left/right scores -------------------------------------
__global__ void lr_kernel(const float* __restrict__ Wh,
                          const float* __restrict__ a,
                          float* __restrict__ hl,
                          float* __restrict__ hr)
{
    const int token = blockIdx.x;
    const int w = threadIdx.x >> 5;
    const int lane = threadIdx.x & 31;
    const int head = w >> 1;
    const int side = w & 1;

    const float* whp = Wh + (size_t)token * HID + head * HD;
    const float* ap = a + head * (2 * HD) + side * HD;
    float s = whp[lane] * ap[lane] + whp[lane + 32] * ap[lane + 32];
#pragma unroll
    for (int o = 16; o; o >>= 1) s += __shfl_xor_sync(0xffffffffu, s, o);
    if (lane == 0) {
        int bidx = token >> 9;
        int i = token & 511;
        float* dst = side ? hr : hl;
        dst[((bidx * HEADS + head) << 9) + i] = s;
    }
}

// ---------------- GAT attention: exp-factorized + tf32 MMA ------------------
__global__ void gat_attn_mma_kernel(const float* __restrict__ Wh,
                                    const float* __restrict__ hl,
                                    const float* __restrict__ hr,
                                    const uint32_t* __restrict__ mb,
                                    float* __restrict__ out)
{
    __shared__ float4 sJF[NN];
    __shared__ float sA1[128], sA2[128], sNL[128];
    __shared__ uint4 sP[4 * 8 * 32];
    __shared__ uint32_t sW[32][68];
    __shared__ float sS[128];
    __shared__ float sRed[16];
    __shared__ float sMax[2];

    const int bx = blockIdx.x;
    const int it = bx & 3;
    const int h = (bx >> 2) & 3;
    const int b = bx >> 4;
    const int tid = threadIdx.x;
    const int w = tid >> 5;
    const int lane = tid & 31;
    const int lg = lane >> 2;
    const int lk = lane & 3;
    const int bh = b * HEADS + h;
    const int i0 = it * 128;

    float lv = 0.f;
    if (tid < 128) lv = hl[(bh << 9) + i0 + tid];
    float rv0 = hr[(bh << 9) + tid];
    float rv1 = hr[(bh << 9) + 256 + tid];

    float lm = (tid < 128) ? lv : -INFINITY;
    float rm = fmaxf(rv0, rv1);
#pragma unroll
    for (int o = 16; o; o >>= 1) {
        lm = fmaxf(lm, __shfl_xor_sync(0xffffffffu, lm, o));
        rm = fmaxf(rm, __shfl_xor_sync(0xffffffffu, rm, o));
    }
    if (lane == 0) { sRed[w] = lm; sRed[8 + w] = rm; }
    __syncthreads();
    if (tid == 0) {
        float L = -INFINITY, R = -INFINITY;
#pragma unroll
        for (int q = 0; q < 8; q++) { L = fmaxf(L, sRed[q]); R = fmaxf(R, sRed[8 + q]); }
        sMax[0] = L; sMax[1] = R;
    }
    __syncthreads();
    const float Lmax = sMax[0], Rmax = sMax[1];
    const float C1 = Lmax + Rmax;

    sJF[tid]       = make_float4(rv0, expf(rv0 - Rmax), expf(0.2f * rv0), 0.f);
    sJF[tid + 256] = make_float4(rv1, expf(rv1 - Rmax), expf(0.2f * rv1), 0.f);
    if (tid < 128) {
        sA1[tid] = expf(lv - Lmax);
        sA2[tid] = expf(0.2f * lv - C1);
        sNL[tid] = -lv;
    }
    __syncthreads();

    const int r0 = w * 16 + lg;
    const int r1 = r0 + 8;
    const float A1a = sA1[r0], A2a = sA2[r0], NLa = sNL[r0];
    const float A1b = sA1[r1], A2b = sA2[r1], NLb = sNL[r1];
    const uint32_t* mrow0 = mb + ((size_t)(b << 9) + i0 + r0) * (NN / 32);
    const uint32_t* mrow1 = mb + ((size_t)(b << 9) + i0 + r1) * (NN / 32);
    float psum0 = 0.f, psum1 = 0.f;

    const int wm16 = (w >> 1) * 2;
    const int wn = (w & 1) * 32;
    float acc[2][4][4];
#pragma unroll
    for (int i = 0; i < 2; i++)
#pragma unroll
        for (int j = 0; j < 4; j++)
#pragma unroll
            for (int r = 0; r < 4; r++) acc[i][j][r] = 0.f;

    const float* whbase = Wh + (size_t)b * NN * HID + h * HD;

    for (int jt = 0; jt < 16; jt++) {
#pragma unroll
        for (int itr = 0; itr < 2; itr++) {
            int f = tid + 256 * itr;
            int jp = f >> 4;
            int dq = (f & 15) * 4;
            float4 v = *reinterpret_cast<const float4*>(whbase + (size_t)(jt * 32 + jp) * HID + dq);
            sW[jp][dq + 0] = f2tf32(v.x);
            sW[jp][dq + 1] = f2tf32(v.y);
            sW[jp][dq + 2] = f2tf32(v.z);
            sW[jp][dq + 3] = f2tf32(v.w);
        }
        uint32_t mw0 = mrow0[jt];
        uint32_t mw1 = mrow1[jt];
#pragma unroll
        for (int kk = 0; kk < 4; kk++) {
            int c0 = kk * 8 + lk;
            int c1 = c0 + 4;
            float4 jf0 = sJF[jt * 32 + c0];
            float4 jf1 = sJF[jt * 32 + c1];
            bool cd00 = (jf0.x >= NLa), cd10 = (jf0.x >= NLb);
            bool cd01 = (jf1.x >= NLa), cd11 = (jf1.x >= NLb);
            float p00 = ((mw0 >> c0) & 1) ? (cd00 ? A1a * jf0.y : A2a * jf0.z) : 0.f;
            float p10 = ((mw1 >> c0) & 1) ? (cd10 ? A1b * jf0.y : A2b * jf0.z) : 0.f;
            float p01 = ((mw0 >> c1) & 1) ? (cd01 ? A1a * jf1.y : A2a * jf1.z) : 0.f;
            float p11 = ((mw1 >> c1) & 1) ? (cd11 ? A1b * jf1.y : A2b * jf1.z) : 0.f;
            psum0 += p00 + p01;
            psum1 += p10 + p11;
            uint4 pk;
            pk.x = f2tf32(p00);
            pk.y = f2tf32(p10);
            pk.z = f2tf32(p01);
            pk.w = f2tf32(p11);
            sP[(kk * 8 + w) * 32 + lane] = pk;
        }
        __syncthreads();

#pragma unroll
        for (int kk = 0; kk < 4; kk++) {
            uint4 av[2];
#pragma unroll
            for (int im = 0; im < 2; im++)
                av[im] = sP[(kk * 8 + wm16 + im) * 32 + lane];
#pragma unroll
            for (int jn = 0; jn < 4; jn++) {
                int nc = wn + jn * 8 + lg;
                uint32_t bf[2];
                bf[0] = sW[kk * 8 + lk][nc];
                bf[1] = sW[kk * 8 + 4 + lk][nc];
#pragma unroll
                for (int im = 0; im < 2; im++)
                    mma_tf32(acc[im][jn],
                             reinterpret_cast<const uint32_t*>(&av[im]), bf);
            }
        }
        __syncthreads();
    }

    psum0 += __shfl_xor_sync(0xffffffffu, psum0, 1);
    psum0 += __shfl_xor_sync(0xffffffffu, psum0, 2);
    psum1 += __shfl_xor_sync(0xffffffffu, psum1, 1);
    psum1 += __shfl_xor_sync(0xffffffffu, psum1, 2);
    if (lk == 0) { sS[r0] = psum0; sS[r1] = psum1; }
    __syncthreads();

#pragma unroll
    for (int im = 0; im < 2; im++) {
#pragma unroll
        for (int half = 0; half < 2; half++) {
            int rloc = (w >> 1) * 32 + im * 16 + lg + half * 8;
            float inv = 1.f / sS[rloc];
            int grow = (b << 9) + i0 + rloc;
#pragma unroll
            for (int jn = 0; jn < 4; jn++) {
                int col = wn + jn * 8 + 2 * lk;
                float2* dst = reinterpret_cast<float2*>(out + (size_t)grow * HID + h * HD + col);
                *dst = make_float2(acc[im][jn][half * 2 + 0] * inv,
                                   acc[im][jn][half * 2 + 1] * inv);
            }
        }
    }
}

// ---------------- GRU gates -> h_temp ----------
__global__ void gru_kernel(const float* __restrict__ gi,
                           const float* __restrict__ gh,
                           const float* __restrict__ hidden,
                           float* __restrict__ h_temp)
{
    int idx = blockIdx.x * blockDim.x + threadIdx.x;
    if (idx >= TOK * HID) return;
    int row = idx / HID;
    int c = idx - row * HID;
    const float* gir = gi + (size_t)row * (3 * HID);
    const float* ghr = gh + (size_t)row * (3 * HID);
    float r = 1.f / (1.f + expf(-(gir[c] + ghr[c])));
    float z = 1.f / (1.f + expf(-(gir[HID + c] + ghr[HID + c])));
    float n = tanhf(gir[2 * HID + c] + r * ghr[2 * HID + c]);
    float hprev = hidden[idx];
    h_temp[idx] = (1.f - z) * n + z * hprev;
}

// ---------------- launch ----------------
extern "C" void kernel_launch(void* const* d_in, const int* in_sizes, int n_in,
                              void* d_out, int out_size)
{
    const float* x        = (const float*)d_in[0];
    const int*   adj      = (const int*)  d_in[1];
    const float* hidden   = (const float*)d_in[2];
    const float* enc_w1   = (const float*)d_in[3];
    const float* enc_b1   = (const float*)d_in[4];
    const float* ln1_g    = (const float*)d_in[5];
    const float* ln1_b    = (const float*)d_in[6];
    const float* enc_w2   = (const float*)d_in[7];
    const float* enc_b2   = (const float*)d_in[8];
    const float* pos      = (const float*)d_in[9];
    const float* gat_w    = (const float*)d_in[10];
    const float* gat_b    = (const float*)d_in[11];
    const float* gat_a    = (const float*)d_in[12];
    const float* gat_ow   = (const float*)d_in[13];
    const float* gat_ob   = (const float*)d_in[14];
    const float* skip_w   = (const float*)d_in[15];
    const float* skip_b   = (const float*)d_in[16];
    const float* gru_wih  = (const float*)d_in[17];
    const float* gru_bih  = (const float*)d_in[18];
    const float* gru_whh  = (const float*)d_in[19];
    const float* gru_bhh  = (const float*)d_in[20];
    const float* dec_w1   = (const float*)d_in[21];
    const float* dec_b1   = (const float*)d_in[22];
    const float* ln2_g    = (const float*)d_in[23];
    const float* ln2_b    = (const float*)d_in[24];
    const float* dec_w2   = (const float*)d_in[25];
    const float* dec_b2   = (const float*)d_in[26];

    float* out = (float*)d_out;
    float* q_out = out;
    float* h_temp_out = out + (size_t)TOK * ACT;

    float *h1, *hsp, *Wh, *hl, *hr, *aout, *hattn, *gi, *gh, *q;
    uint32_t* mbits;
    cudaGetSymbolAddress((void**)&h1,    g_h1);
    cudaGetSymbolAddress((void**)&hsp,   g_hsp);
    cudaGetSymbolAddress((void**)&Wh,    g_Wh);
    cudaGetSymbolAddress((void**)&hl,    g_hl);
    cudaGetSymbolAddress((void**)&hr,    g_hr);
    cudaGetSymbolAddress((void**)&aout,  g_aout);
    cudaGetSymbolAddress((void**)&hattn, g_hattn);
    cudaGetSymbolAddress((void**)&gi,    g_gi);
    cudaGetSymbolAddress((void**)&gh,    g_gh);
    cudaGetSymbolAddress((void**)&q,     g_q);
    cudaGetSymbolAddress((void**)&mbits, g_mbits);

    static int smem_set = 0;
    if (!smem_set) {
        cudaFuncSetAttribute(gemm_tf32_kernel,
                             cudaFuncAttributeMaxDynamicSharedMemorySize,
                             GEMM_SMEM_BYTES);
        smem_set = 1;
    }

    const int MB = TOK / 128;
    const size_t SH = GEMM_SMEM_BYTES;

    pack_adj_kernel<<<TOK, 512>>>(adj, mbits);

    // encoder
    gemm_tf32_kernel<<<dim3(HID2 / 64, MB), 256, SH>>>(x, enc_w1, enc_b1, nullptr, h1, TOK, HID2, IND, 0);
    ln_gelu_kernel<<<TOK, 256>>>(h1, ln1_g, ln1_b, HID2);
    gemm_tf32_kernel<<<dim3(HID / 64, MB), 256, SH>>>(h1, enc_w2, enc_b2, pos, hsp, TOK, HID, HID2, 0);

    // GAT
    gemm_tf32_kernel<<<dim3(HID / 64, MB), 256, SH>>>(hsp, gat_w, gat_b, nullptr, Wh, TOK, HID, HID, 0);
    lr_kernel<<<TOK, 256>>>(Wh, gat_a, hl, hr);
    gat_attn_mma_kernel<<<BB * HEADS * 4, 256>>>(Wh, hl, hr, mbits, aout);

    // out-proj + skip
    gemm_tf32_kernel<<<dim3(HID / 64, MB), 256, SH>>>(aout, gat_ow, gat_ob, skip_b, hattn, TOK, HID, HID, 0);
    gemm_tf32_kernel<<<dim3(HID / 64, MB), 256, SH>>>(hsp, skip_w, nullptr, nullptr, hattn, TOK, HID, HID, 1);

    // GRU
    gemm_tf32_kernel<<<dim3(3 * HID / 64, MB), 256, SH>>>(hattn,  gru_wih, gru_bih, nullptr, gi, TOK, 3 * HID, HID, 0);
    gemm_tf32_kernel<<<dim3(3 * HID / 64, MB), 256, SH>>>(hidden, gru_whh, gru_bhh, nullptr, gh, TOK, 3 * HID, HID, 0);
    gru_kernel<<<(TOK * HID + 255) / 256, 256>>>(gi, gh, hidden, h_temp_out);

    // decoder
    gemm_tf32_kernel<<<dim3(HID / 64, MB), 256, SH>>>(h_temp_out, dec_w1, dec_b1, nullptr, q, TOK, HID, HID, 0);
    ln_gelu_kernel<<<TOK, 256>>>(q, ln2_g, ln2_b, HID);
    gemm_tf32_kernel<<<dim3(1, MB), 256, SH>>>(q, dec_w2, dec_b2, nullptr, q_out, TOK, ACT, HID, 0);
}

// round 6
// speedup vs baseline: 4.8346x; 1.0647x over previous
#include <cuda_runtime.h>
#include <math.h>
#include <stdint.h>

// ---------------- problem constants ----------------
#define BB   32
#define NN   512
#define IND  128
#define HID  256
#define HID2 512
#define HEADS 4
#define HD   64
#define ACT  32
#define TOK  (BB*NN)            // 16384 tokens

// GEMM smem geometry
#define AST  36                 // row stride in words (32 k + 4 pad)
#define A_WORDS (128 * AST)
#define W_WORDS (64 * AST)
#define GEMM_SMEM_BYTES ((2 * A_WORDS + 2 * W_WORDS) * 4)   // 55296

// ---------------- scratch (device globals) --------
__device__ float g_h1[TOK * HID2];
__device__ float g_hsp[TOK * HID];
__device__ float g_Wh[TOK * HID];
__device__ float g_hl[BB * HEADS * NN];
__device__ float g_hr[BB * HEADS * NN];
__device__ float g_aout[TOK * HID];
__device__ float g_hattn[TOK * HID];
__device__ float g_gsum[TOK * HID2];        // fused r,z gate pre-activations
__device__ float g_in_[TOK * HID];          // i_n
__device__ float g_hn_[TOK * HID];          // h_n
__device__ float g_q[TOK * HID];
__device__ uint32_t g_mbits[(size_t)BB * NN * (NN / 32)];

// ---------------- tf32 / mma helpers ----------------
__device__ __forceinline__ uint32_t f2tf32(float f) {
    uint32_t r;
    asm("cvt.rna.tf32.f32 %0, %1;" : "=r"(r) : "f"(f));
    return r;
}

__device__ __forceinline__ void mma_tf32(float* d, const uint32_t* a, const uint32_t* b) {
    asm volatile(
        "mma.sync.aligned.m16n8k8.row.col.f32.tf32.tf32.f32 "
        "{%0,%1,%2,%3},{%4,%5,%6,%7},{%8,%9},{%0,%1,%2,%3};"
        : "+f"(d[0]), "+f"(d[1]), "+f"(d[2]), "+f"(d[3])
        : "r"(a[0]), "r"(a[1]), "r"(a[2]), "r"(a[3]),
          "r"(b[0]), "r"(b[1]));
}

__device__ __forceinline__ void ldsm4(uint32_t& r0, uint32_t& r1, uint32_t& r2, uint32_t& r3,
                                      uint32_t addr) {
    asm volatile("ldmatrix.sync.aligned.m8n8.x4.shared.b16 {%0,%1,%2,%3}, [%4];"
                 : "=r"(r0), "=r"(r1), "=r"(r2), "=r"(r3) : "r"(addr));
}

// ---------------- TF32 NT GEMM, dual-source K-concat, ldmatrix inner loop ---
// C[M,N] = [A|A2][M,K1+K2] @ [W|W2][N,K1+K2]^T (+b1) (+b2)
// BM=128, BN=64, BK=32, 256 thr. K1,K2 multiples of 32 (K2 may be 0).
__global__ void __launch_bounds__(256, 3)
gemm_tf32_kernel(const float* __restrict__ A,  const float* __restrict__ A2,
                 const float* __restrict__ W,  const float* __restrict__ W2,
                 const float* __restrict__ b1, const float* __restrict__ b2,
                 float* __restrict__ C,
                 int M, int N, int K1, int K2)
{
    extern __shared__ uint32_t smem[];
    uint32_t* Asm = smem;
    uint32_t* Wsm = smem + 2 * A_WORDS;

    const int m0 = blockIdx.y * 128;
    const int n0 = blockIdx.x * 64;
    const int tid = threadIdx.x;
    const int w = tid >> 5;
    const int lane = tid & 31;
    const int lg = lane >> 2;
    const int lk = lane & 3;
    const int wm = (w >> 1) * 32;
    const int wn = (w & 1) * 32;

    // ldmatrix lane address roles
    const int g8  = lane >> 3;    // 0..3 matrix group
    const int r8  = lane & 7;     // row within matrix
    const int ghf = g8 >> 1;      // high bit
    const int glf = g8 & 1;       // low bit

    float acc[2][4][4];
#pragma unroll
    for (int i = 0; i < 2; i++)
#pragma unroll
        for (int j = 0; j < 4; j++)
#pragma unroll
            for (int r = 0; r < 4; r++) acc[i][j][r] = 0.f;

    const int ar = tid >> 3;            // 0..31  (A rows ar, +32, +64, +96)
    const int ac4 = (tid & 7) * 4;      // k word offset 0..28
    const int nt = (K1 + K2) >> 5;
    const int nt1 = K1 >> 5;

    // byte offsets within a smem buffer for ldmatrix (per im / per p)
    uint32_t offA[2], offB[2];
#pragma unroll
    for (int im = 0; im < 2; im++)
        offA[im] = ((wm + im * 16 + glf * 8 + r8) * AST + ghf * 4) * 4;
#pragma unroll
    for (int p = 0; p < 2; p++)
        offB[p] = ((wn + p * 16 + ghf * 8 + r8) * AST + glf * 4) * 4;

    const uint32_t AsmAddr = (uint32_t)__cvta_generic_to_shared(Asm);
    const uint32_t WsmAddr = (uint32_t)__cvta_generic_to_shared(Wsm);

    float4 aReg[4];
    float4 wReg[2];

    // ---- prologue: load tile 0 to regs ----
    {
        const float* Ap = (0 < nt1) ? A : A2;
        int lda = (0 < nt1) ? K1 : K2;
#pragma unroll
        for (int i = 0; i < 4; i++)
            aReg[i] = *reinterpret_cast<const float4*>(Ap + (size_t)(m0 + ar + 32 * i) * lda + ac4);
        const float* Wp = (0 < nt1) ? W : W2;
#pragma unroll
        for (int i = 0; i < 2; i++) {
            int r = ar + 32 * i;
            if (n0 + r < N)
                wReg[i] = *reinterpret_cast<const float4*>(Wp + (size_t)(n0 + r) * lda + ac4);
            else
                wReg[i] = make_float4(0.f, 0.f, 0.f, 0.f);
        }
    }

    for (int t = 0; t < nt; t++) {
        uint32_t* Ab = Asm + (t & 1) * A_WORDS;
        uint32_t* Wb = Wsm + (t & 1) * W_WORDS;
        const uint32_t AbA = AsmAddr + (t & 1) * (A_WORDS * 4);
        const uint32_t WbA = WsmAddr + (t & 1) * (W_WORDS * 4);

        // ---- store staged regs (STS.128, conflict-free) ----
#pragma unroll
        for (int i = 0; i < 4; i++) {
            uint4 pv;
            pv.x = f2tf32(aReg[i].x); pv.y = f2tf32(aReg[i].y);
            pv.z = f2tf32(aReg[i].z); pv.w = f2tf32(aReg[i].w);
            *reinterpret_cast<uint4*>(&Ab[(ar + 32 * i) * AST + ac4]) = pv;
        }
#pragma unroll
        for (int i = 0; i < 2; i++) {
            uint4 pv;
            pv.x = f2tf32(wReg[i].x); pv.y = f2tf32(wReg[i].y);
            pv.z = f2tf32(wReg[i].z); pv.w = f2tf32(wReg[i].w);
            *reinterpret_cast<uint4*>(&Wb[(ar + 32 * i) * AST + ac4]) = pv;
        }

        // ---- prefetch next tile ----
        if (t + 1 < nt) {
            int tn = t + 1;
            const float* Ap; const float* Wp; int lda, kof;
            if (tn < nt1) { Ap = A;  Wp = W;  lda = K1; kof = tn * 32; }
            else          { Ap = A2; Wp = W2; lda = K2; kof = tn * 32 - K1; }
            kof += ac4;
#pragma unroll
            for (int i = 0; i < 4; i++)
                aReg[i] = *reinterpret_cast<const float4*>(Ap + (size_t)(m0 + ar + 32 * i) * lda + kof);
#pragma unroll
            for (int i = 0; i < 2; i++) {
                int r = ar + 32 * i;
                if (n0 + r < N)
                    wReg[i] = *reinterpret_cast<const float4*>(Wp + (size_t)(n0 + r) * lda + kof);
                else
                    wReg[i] = make_float4(0.f, 0.f, 0.f, 0.f);
            }
        }

        __syncthreads();

        // ---- 4 k-octets: 4 LDSM.x4 + 8 MMA each ----
#pragma unroll
        for (int kk = 0; kk < 4; kk++) {
            uint32_t af[2][4];
            uint32_t bf[4][2];
#pragma unroll
            for (int im = 0; im < 2; im++)
                ldsm4(af[im][0], af[im][1], af[im][2], af[im][3],
                      AbA + offA[im] + kk * 32);
#pragma unroll
            for (int p = 0; p < 2; p++)
                ldsm4(bf[2 * p][0], bf[2 * p][1], bf[2 * p + 1][0], bf[2 * p + 1][1],
                      WbA + offB[p] + kk * 32);
#pragma unroll
            for (int im = 0; im < 2; im++)
#pragma unroll
                for (int jn = 0; jn < 4; jn++)
                    mma_tf32(acc[im][jn], af[im], bf[jn]);
        }
        // next STS targets the other buffer; the barrier above protects reuse.
    }

    // ---- epilogue ----
#pragma unroll
    for (int im = 0; im < 2; im++) {
#pragma unroll
        for (int jn = 0; jn < 4; jn++) {
            int col0 = n0 + wn + jn * 8 + 2 * lk;
            if (col0 >= N) continue;
            float bias0 = 0.f, bias1 = 0.f;
            if (b1) { bias0 += b1[col0]; bias1 += b1[col0 + 1]; }
            if (b2) { bias0 += b2[col0]; bias1 += b2[col0 + 1]; }
#pragma unroll
            for (int half = 0; half < 2; half++) {
                int row = m0 + wm + im * 16 + lg + half * 8;
                float v0 = acc[im][jn][half * 2 + 0] + bias0;
                float v1 = acc[im][jn][half * 2 + 1] + bias1;
                *reinterpret_cast<float2*>(C + (size_t)row * N + col0) = make_float2(v0, v1);
            }
        }
    }
}

// ---------------- fused LayerNorm + exact GELU (in place) ----
__device__ __forceinline__ float gelu_exact(float x) {
    return 0.5f * x * (1.0f + erff(x * 0.70710678118654752440f));
}

__global__ void ln_gelu_kernel(float* __restrict__ X,
                               const float* __restrict__ g,
                               const float* __restrict__ b,
                               int D)
{
    __shared__ float sS[8], sQ[8];
    float* row = X + (size_t)blockIdx.x * D;
    const int t = threadIdx.x;
    const int w = t >> 5;
    const int lane = t & 31;

    float v0 = row[t];
    float v1 = (D > 256) ? row[t + 256] : 0.f;

    float s = v0 + v1;
    float q = v0 * v0 + v1 * v1;
#pragma unroll
    for (int o = 16; o; o >>= 1) {
        s += __shfl_xor_sync(0xffffffffu, s, o);
        q += __shfl_xor_sync(0xffffffffu, q, o);
    }
    if (lane == 0) { sS[w] = s; sQ[w] = q; }
    __syncthreads();
    float ts = 0.f, tq = 0.f;
#pragma unroll
    for (int i = 0; i < 8; i++) { ts += sS[i]; tq += sQ[i]; }
    float mean = ts / (float)D;
    float var = tq / (float)D - mean * mean;
    float rstd = rsqrtf(var + 1e-5f);

    row[t] = gelu_exact((v0 - mean) * rstd * g[t] + b[t]);
    if (D > 256)
        row[t + 256] = gelu_exact((v1 - mean) * rstd * g[t + 256] + b[t + 256]);
}

// ---------------- pack adjacency into bitmasks ------------------------------
__global__ void pack_adj_kernel(const int* __restrict__ adj, uint32_t* __restrict__ mb)
{
    int row = blockIdx.x;
    int t = threadIdx.x;
    int v = adj[(size_t)row * NN + t];
    unsigned bal = __ballot_sync(0xffffffffu, v != 0);
    if ((t & 31) == 0) mb[row * (NN / 32) + (t >> 5)] = bal;
}

// ---------------- GAT left/right scores -------------------------------------
__global__ void lr_kernel(const float* __restrict__ Wh,
                          const float* __restrict__ a,
                          float* __restrict__ hl,
                          float* __restrict__ hr)
{
    const int token = blockIdx.x;
    const int w = threadIdx.x >> 5;
    const int lane = threadIdx.x & 31;
    const int head = w >> 1;
    const int side = w & 1;

    const float* whp = Wh + (size_t)token * HID + head * HD;
    const float* ap = a + head * (2 * HD) + side * HD;
    float s = whp[lane] * ap[lane] + whp[lane + 32] * ap[lane + 32];
#pragma unroll
    for (int o = 16; o; o >>= 1) s += __shfl_xor_sync(0xffffffffu, s, o);
    if (lane == 0) {
        int bidx = token >> 9;
        int i = token & 511;
        float* dst = side ? hr : hl;
        dst[((bidx * HEADS + head) << 9) + i] = s;
    }
}

// ---------------- GAT attention: exp-factorized + tf32 MMA ------------------
__global__ void gat_attn_mma_kernel(const float* __restrict__ Wh,
                                    const float* __restrict__ hl,
                                    const float* __restrict__ hr,
                                    const uint32_t* __restrict__ mb,
                                    float* __restrict__ out)
{
    __shared__ float4 sJF[NN];
    __shared__ float sA1[128], sA2[128], sNL[128];
    __shared__ uint4 sP[4 * 8 * 32];
    __shared__ uint32_t sW[32][68];
    __shared__ float sS[128];
    __shared__ float sRed[16];
    __shared__ float sMax[2];

    const int bx = blockIdx.x;
    const int it = bx & 3;
    const int h = (bx >> 2) & 3;
    const int b = bx >> 4;
    const int tid = threadIdx.x;
    const int w = tid >> 5;
    const int lane = tid & 31;
    const int lg = lane >> 2;
    const int lk = lane & 3;
    const int bh = b * HEADS + h;
    const int i0 = it * 128;

    float lv = 0.f;
    if (tid < 128) lv = hl[(bh << 9) + i0 + tid];
    float rv0 = hr[(bh << 9) + tid];
    float rv1 = hr[(bh << 9) + 256 + tid];

    float lm = (tid < 128) ? lv : -INFINITY;
    float rm = fmaxf(rv0, rv1);
#pragma unroll
    for (int o = 16; o; o >>= 1) {
        lm = fmaxf(lm, __shfl_xor_sync(0xffffffffu, lm, o));
        rm = fmaxf(rm, __shfl_xor_sync(0xffffffffu, rm, o));
    }
    if (lane == 0) { sRed[w] = lm; sRed[8 + w] = rm; }
    __syncthreads();
    if (tid == 0) {
        float L = -INFINITY, R = -INFINITY;
#pragma unroll
        for (int q = 0; q < 8; q++) { L = fmaxf(L, sRed[q]); R = fmaxf(R, sRed[8 + q]); }
        sMax[0] = L; sMax[1] = R;
    }
    __syncthreads();
    const float Lmax = sMax[0], Rmax = sMax[1];
    const float C1 = Lmax + Rmax;

    sJF[tid]       = make_float4(rv0, expf(rv0 - Rmax), expf(0.2f * rv0), 0.f);
    sJF[tid + 256] = make_float4(rv1, expf(rv1 - Rmax), expf(0.2f * rv1), 0.f);
    if (tid < 128) {
        sA1[tid] = expf(lv - Lmax);
        sA2[tid] = expf(0.2f * lv - C1);
        sNL[tid] = -lv;
    }
    __syncthreads();

    const int r0 = w * 16 + lg;
    const int r1 = r0 + 8;
    const float A1a = sA1[r0], A2a = sA2[r0], NLa = sNL[r0];
    const float A1b = sA1[r1], A2b = sA2[r1], NLb = sNL[r1];
    const uint32_t* mrow0 = mb + ((size_t)(b << 9) + i0 + r0) * (NN / 32);
    const uint32_t* mrow1 = mb + ((size_t)(b << 9) + i0 + r1) * (NN / 32);
    float psum0 = 0.f, psum1 = 0.f;

    const int wm16 = (w >> 1) * 2;
    const int wn = (w & 1) * 32;
    float acc[2][4][4];
#pragma unroll
    for (int i = 0; i < 2; i++)
#pragma unroll
        for (int j = 0; j < 4; j++)
#pragma unroll
            for (int r = 0; r < 4; r++) acc[i][j][r] = 0.f;

    const float* whbase = Wh + (size_t)b * NN * HID + h * HD;

    for (int jt = 0; jt < 16; jt++) {
#pragma unroll
        for (int itr = 0; itr < 2; itr++) {
            int f = tid + 256 * itr;
            int jp = f >> 4;
            int dq = (f & 15) * 4;
            float4 v = *reinterpret_cast<const float4*>(whbase + (size_t)(jt * 32 + jp) * HID + dq);
            sW[jp][dq + 0] = f2tf32(v.x);
            sW[jp][dq + 1] = f2tf32(v.y);
            sW[jp][dq + 2] = f2tf32(v.z);
            sW[jp][dq + 3] = f2tf32(v.w);
        }
        uint32_t mw0 = mrow0[jt];
        uint32_t mw1 = mrow1[jt];
#pragma unroll
        for (int kk = 0; kk < 4; kk++) {
            int c0 = kk * 8 + lk;
            int c1 = c0 + 4;
            float4 jf0 = sJF[jt * 32 + c0];
            float4 jf1 = sJF[jt * 32 + c1];
            bool cd00 = (jf0.x >= NLa), cd10 = (jf0.x >= NLb);
            bool cd01 = (jf1.x >= NLa), cd11 = (jf1.x >= NLb);
            float p00 = ((mw0 >> c0) & 1) ? (cd00 ? A1a * jf0.y : A2a * jf0.z) : 0.f;
            float p10 = ((mw1 >> c0) & 1) ? (cd10 ? A1b * jf0.y : A2b * jf0.z) : 0.f;
            float p01 = ((mw0 >> c1) & 1) ? (cd01 ? A1a * jf1.y : A2a * jf1.z) : 0.f;
            float p11 = ((mw1 >> c1) & 1) ? (cd11 ? A1b * jf1.y : A2b * jf1.z) : 0.f;
            psum0 += p00 + p01;
            psum1 += p10 + p11;
            uint4 pk;
            pk.x = f2tf32(p00);
            pk.y = f2tf32(p10);
            pk.z = f2tf32(p01);
            pk.w = f2tf32(p11);
            sP[(kk * 8 + w) * 32 + lane] = pk;
        }
        __syncthreads();

#pragma unroll
        for (int kk = 0; kk < 4; kk++) {
            uint4 av[2];
#pragma unroll
            for (int im = 0; im < 2; im++)
                av[im] = sP[(kk * 8 + wm16 + im) * 32 + lane];
#pragma unroll
            for (int jn = 0; jn < 4; jn++) {
                int nc = wn + jn * 8 + lg;
                uint32_t bf[2];
                bf[0] = sW[kk * 8 + lk][nc];
                bf[1] = sW[kk * 8 + 4 + lk][nc];
#pragma unroll
                for (int im = 0; im < 2; im++)
                    mma_tf32(acc[im][jn],
                             reinterpret_cast<const uint32_t*>(&av[im]), bf);
            }
        }
        __syncthreads();
    }

    psum0 += __shfl_xor_sync(0xffffffffu, psum0, 1);
    psum0 += __shfl_xor_sync(0xffffffffu, psum0, 2);
    psum1 += __shfl_xor_sync(0xffffffffu, psum1, 1);
    psum1 += __shfl_xor_sync(0xffffffffu, psum1, 2);
    if (lk == 0) { sS[r0] = psum0; sS[r1] = psum1; }
    __syncthreads();

#pragma unroll
    for (int im = 0; im < 2; im++) {
#pragma unroll
        for (int half = 0; half < 2; half++) {
            int rloc = (w >> 1) * 32 + im * 16 + lg + half * 8;
            float inv = 1.f / sS[rloc];
            int grow = (b << 9) + i0 + rloc;
#pragma unroll
            for (int jn = 0; jn < 4; jn++) {
                int col = wn + jn * 8 + 2 * lk;
                float2* dst = reinterpret_cast<float2*>(out + (size_t)grow * HID + h * HD + col);
                *dst = make_float2(acc[im][jn][half * 2 + 0] * inv,
                                   acc[im][jn][half * 2 + 1] * inv);
            }
        }
    }
}

// ---------------- GRU gates -> h_temp ----------
// gsum: [TOK, 512] fused (i_r+h_r | i_z+h_z); in_/hn_: [TOK, 256]
__global__ void gru_kernel(const float* __restrict__ gsum,
                           const float* __restrict__ in_,
                           const float* __restrict__ hn_,
                           const float* __restrict__ hidden,
                           float* __restrict__ h_temp)
{
    int idx = blockIdx.x * blockDim.x + threadIdx.x;
    if (idx >= TOK * HID) return;
    int row = idx >> 8;
    int c = idx & 255;
    const float* gs = gsum + ((size_t)row << 9);
    float r = 1.f / (1.f + expf(-gs[c]));
    float z = 1.f / (1.f + expf(-gs[HID + c]));
    float n = tanhf(in_[idx] + r * hn_[idx]);
    h_temp[idx] = (1.f - z) * n + z * hidden[idx];
}

// ---------------- launch ----------------
extern "C" void kernel_launch(void* const* d_in, const int* in_sizes, int n_in,
                              void* d_out, int out_size)
{
    const float* x        = (const float*)d_in[0];
    const int*   adj      = (const int*)  d_in[1];
    const float* hidden   = (const float*)d_in[2];
    const float* enc_w1   = (const float*)d_in[3];
    const float* enc_b1   = (const float*)d_in[4];
    const float* ln1_g    = (const float*)d_in[5];
    const float* ln1_b    = (const float*)d_in[6];
    const float* enc_w2   = (const float*)d_in[7];
    const float* enc_b2   = (const float*)d_in[8];
    const float* pos      = (const float*)d_in[9];
    const float* gat_w    = (const float*)d_in[10];
    const float* gat_b    = (const float*)d_in[11];
    const float* gat_a    = (const float*)d_in[12];
    const float* gat_ow   = (const float*)d_in[13];
    const float* gat_ob   = (const float*)d_in[14];
    const float* skip_w   = (const float*)d_in[15];
    const float* skip_b   = (const float*)d_in[16];
    const float* gru_wih  = (const float*)d_in[17];
    const float* gru_bih  = (const float*)d_in[18];
    const float* gru_whh  = (const float*)d_in[19];
    const float* gru_bhh  = (const float*)d_in[20];
    const float* dec_w1   = (const float*)d_in[21];
    const float* dec_b1   = (const float*)d_in[22];
    const float* ln2_g    = (const float*)d_in[23];
    const float* ln2_b    = (const float*)d_in[24];
    const float* dec_w2   = (const float*)d_in[25];
    const float* dec_b2   = (const float*)d_in[26];

    float* out = (float*)d_out;
    float* q_out = out;
    float* h_temp_out = out + (size_t)TOK * ACT;

    float *h1, *hsp, *Wh, *hl, *hr, *aout, *hattn, *gsum, *in_, *hn_, *q;
    uint32_t* mbits;
    cudaGetSymbolAddress((void**)&h1,    g_h1);
    cudaGetSymbolAddress((void**)&hsp,   g_hsp);
    cudaGetSymbolAddress((void**)&Wh,    g_Wh);
    cudaGetSymbolAddress((void**)&hl,    g_hl);
    cudaGetSymbolAddress((void**)&hr,    g_hr);
    cudaGetSymbolAddress((void**)&aout,  g_aout);
    cudaGetSymbolAddress((void**)&hattn, g_hattn);
    cudaGetSymbolAddress((void**)&gsum,  g_gsum);
    cudaGetSymbolAddress((void**)&in_,   g_in_);
    cudaGetSymbolAddress((void**)&hn_,   g_hn_);
    cudaGetSymbolAddress((void**)&q,     g_q);
    cudaGetSymbolAddress((void**)&mbits, g_mbits);

    cudaFuncSetAttribute(gemm_tf32_kernel,
                         cudaFuncAttributeMaxDynamicSharedMemorySize,
                         GEMM_SMEM_BYTES);

    const int MB = TOK / 128;
    const size_t SH = GEMM_SMEM_BYTES;

    pack_adj_kernel<<<TOK, 512>>>(adj, mbits);

    // encoder
    gemm_tf32_kernel<<<dim3(HID2 / 64, MB), 256, SH>>>(
        x, nullptr, enc_w1, nullptr, enc_b1, nullptr, h1, TOK, HID2, IND, 0);
    ln_gelu_kernel<<<TOK, 256>>>(h1, ln1_g, ln1_b, HID2);
    gemm_tf32_kernel<<<dim3(HID / 64, MB), 256, SH>>>(
        h1, nullptr, enc_w2, nullptr, enc_b2, pos, hsp, TOK, HID, HID2, 0);

    // GAT
    gemm_tf32_kernel<<<dim3(HID / 64, MB), 256, SH>>>(
        hsp, nullptr, gat_w, nullptr, gat_b, nullptr, Wh, TOK, HID, HID, 0);
    lr_kernel<<<TOK, 256>>>(Wh, gat_a, hl, hr);
    gat_attn_mma_kernel<<<BB * HEADS * 4, 256>>>(Wh, hl, hr, mbits, aout);

    // fused out-proj + skip: hattn = aout@gat_ow^T + hsp@skip_w^T + gat_ob + skip_b
    gemm_tf32_kernel<<<dim3(HID / 64, MB), 256, SH>>>(
        aout, hsp, gat_ow, skip_w, gat_ob, skip_b, hattn, TOK, HID, HID, HID);

    // GRU: fused r,z GEMM over K-concat [hattn|hidden]; separate i_n, h_n
    gemm_tf32_kernel<<<dim3(HID2 / 64, MB), 256, SH>>>(
        hattn, hidden, gru_wih, gru_whh, gru_bih, gru_bhh, gsum, TOK, HID2, HID, HID);
    gemm_tf32_kernel<<<dim3(HID / 64, MB), 256, SH>>>(
        hattn, nullptr, gru_wih + 2 * HID * HID, nullptr, gru_bih + 2 * HID, nullptr,
        in_, TOK, HID, HID, 0);
    gemm_tf32_kernel<<<dim3(HID / 64, MB), 256, SH>>>(
        hidden, nullptr, gru_whh + 2 * HID * HID, nullptr, gru_bhh + 2 * HID, nullptr,
        hn_, TOK, HID, HID, 0);
    gru_kernel<<<(TOK * HID + 255) / 256, 256>>>(gsum, in_, hn_, hidden, h_temp_out);

    // decoder
    gemm_tf32_kernel<<<dim3(HID / 64, MB), 256, SH>>>(
        h_temp_out, nullptr, dec_w1, nullptr, dec_b1, nullptr, q, TOK, HID, HID, 0);
    ln_gelu_kernel<<<TOK, 256>>>(q, ln2_g, ln2_b, HID);
    gemm_tf32_kernel<<<dim3(1, MB), 256, SH>>>(
        q, nullptr, dec_w2, nullptr, dec_b2, nullptr, q_out, TOK, ACT, HID, 0);
}

// round 9
// speedup vs baseline: 5.1837x; 1.0722x over previous
#include <cuda_runtime.h>
#include <math.h>
#include <stdint.h>

// ---------------- problem constants ----------------
#define BB   32
#define NN   512
#define IND  128
#define HID  256
#define HID2 512
#define HEADS 4
#define HD   64
#define ACT  32
#define TOK  (BB*NN)            // 16384 tokens

// GEMM smem geometry: [row][k] stride-36 words, double buffered
#define AST  36
#define A_WORDS (128 * AST)
#define W_WORDS (64 * AST)
#define A_BYTES (A_WORDS * 4)
#define STAGE_BYTES ((A_WORDS + W_WORDS) * 4)     // 27648
#define GEMM_SMEM_BYTES (2 * STAGE_BYTES)         // 55296

// ---------------- scratch (device globals) --------
__device__ float g_h1[TOK * HID2];
__device__ float g_hsp[TOK * HID];
__device__ float g_Wh[TOK * HID];
__device__ float g_hl[BB * HEADS * NN];
__device__ float g_hr[BB * HEADS * NN];
__device__ float g_aout[TOK * HID];
__device__ float g_hattn[TOK * HID];
__device__ float g_gsum[TOK * HID2];
__device__ float g_in_[TOK * HID];
__device__ float g_hn_[TOK * HID];
__device__ float g_q[TOK * HID];
__device__ float g_xc[TOK * IND];          // tf32 copies of inputs
__device__ float g_hidc[TOK * HID];
__device__ float g_htc[TOK * HID];
__device__ float g_wc[860160];             // tf32 copies of all weights
__device__ uint32_t g_mbits[(size_t)BB * NN * (NN / 32)];

// weight offsets in g_wc (floats)
#define WC_ENC1 0
#define WC_ENC2 65536
#define WC_GAT  196608
#define WC_OW   262144
#define WC_SKIP 327680
#define WC_WIH  393216
#define WC_WHH  589824
#define WC_DEC1 786432
#define WC_DEC2 851968

// ---------------- helpers ----------------
__device__ __forceinline__ uint32_t f2tf32(float f) {
    uint32_t r;
    asm("cvt.rna.tf32.f32 %0, %1;" : "=r"(r) : "f"(f));
    return r;
}

__device__ __forceinline__ void mma_tf32(float* d, const uint32_t* a, const uint32_t* b) {
    asm volatile(
        "mma.sync.aligned.m16n8k8.row.col.f32.tf32.tf32.f32 "
        "{%0,%1,%2,%3},{%4,%5,%6,%7},{%8,%9},{%0,%1,%2,%3};"
        : "+f"(d[0]), "+f"(d[1]), "+f"(d[2]), "+f"(d[3])
        : "r"(a[0]), "r"(a[1]), "r"(a[2]), "r"(a[3]),
          "r"(b[0]), "r"(b[1]));
}

__device__ __forceinline__ void ldsm4(uint32_t& r0, uint32_t& r1, uint32_t& r2, uint32_t& r3,
                                      uint32_t addr) {
    asm volatile("ldmatrix.sync.aligned.m8n8.x4.shared.b16 {%0,%1,%2,%3}, [%4];"
                 : "=r"(r0), "=r"(r1), "=r"(r2), "=r"(r3) : "r"(addr));
}

__device__ __forceinline__ void cpa16(uint32_t dst, const void* src, int srcsize) {
    asm volatile("cp.async.ca.shared.global [%0], [%1], 16, %2;"
                 :: "r"(dst), "l"(src), "r"(srcsize) : "memory");
}
#define CP_COMMIT() asm volatile("cp.async.commit_group;" ::: "memory")
#define CP_WAIT0()  asm volatile("cp.async.wait_group 0;" ::: "memory")

// ---------------- one-shot tf32 conversion of inputs + weights --------------
__global__ void cvt_all_kernel(const float* __restrict__ x, const float* __restrict__ hidden,
    const float* __restrict__ w_e1, const float* __restrict__ w_e2,
    const float* __restrict__ w_g,  const float* __restrict__ w_ow,
    const float* __restrict__ w_sk, const float* __restrict__ w_ih,
    const float* __restrict__ w_hh, const float* __restrict__ w_d1,
    const float* __restrict__ w_d2,
    float* __restrict__ xc, float* __restrict__ hidc, float* __restrict__ wc)
{
    const int NX = 524288, NH = 1048576;   // float4 counts
    int i = blockIdx.x * blockDim.x + threadIdx.x;
    const float4* src; float4* dst;
    if (i < NX) { src = (const float4*)x + i; dst = (float4*)xc + i; }
    else if (i < NX + NH) { int j = i - NX; src = (const float4*)hidden + j; dst = (float4*)hidc + j; }
    else {
        int j = i - (NX + NH);
        if (j >= 215040) return;
        const float* s; int o;
        if      (j < 16384)  { s = w_e1; o = j; }
        else if (j < 49152)  { s = w_e2; o = j - 16384; }
        else if (j < 65536)  { s = w_g;  o = j - 49152; }
        else if (j < 81920)  { s = w_ow; o = j - 65536; }
        else if (j < 98304)  { s = w_sk; o = j - 81920; }
        else if (j < 147456) { s = w_ih; o = j - 98304; }
        else if (j < 196608) { s = w_hh; o = j - 147456; }
        else if (j < 212992) { s = w_d1; o = j - 196608; }
        else                 { s = w_d2; o = j - 212992; }
        src = (const float4*)s + o; dst = (float4*)wc + j;
    }
    float4 v = *src;
    float4 r;
    r.x = __uint_as_float(f2tf32(v.x));
    r.y = __uint_as_float(f2tf32(v.y));
    r.z = __uint_as_float(f2tf32(v.z));
    r.w = __uint_as_float(f2tf32(v.w));
    *dst = r;
}

// ---------------- TF32 NT GEMM, cp.async pipeline, dual-source K-concat -----
// C[M,N] = [A|A2][M,K1+K2] @ [W|W2][N,K1+K2]^T (+b1) (+b2); cvt -> tf32-round C.
// All sources MUST already hold tf32-rounded values. BM=128, BN=64, BK=32.
#define ISSUE_TILE(t_) do {                                                    \
    int _t = (t_);                                                             \
    const float* _Ap; const float* _Wp; int _lda, _kof;                        \
    if (_t < nt1) { _Ap = A; _Wp = W; _lda = K1; _kof = _t * 32; }             \
    else { _Ap = A2; _Wp = W2; _lda = K2; _kof = _t * 32 - K1; }               \
    _kof += ac4;                                                               \
    uint32_t _sb = sbase + (_t & 1) * STAGE_BYTES;                             \
    _Pragma("unroll")                                                          \
    for (int _i = 0; _i < 4; _i++)                                             \
        cpa16(_sb + stA[_i], _Ap + (size_t)(m0 + ar + 32 * _i) * _lda + _kof, 16); \
    _Pragma("unroll")                                                          \
    for (int _i = 0; _i < 2; _i++)                                             \
        cpa16(_sb + stB[_i], _Wp + (size_t)(n0 + ar + 32 * _i) * _lda + _kof, bvalid[_i]); \
    CP_COMMIT();                                                               \
} while (0)

__global__ void __launch_bounds__(256, 3)
gemm_tf32_kernel(const float* __restrict__ A,  const float* __restrict__ A2,
                 const float* __restrict__ W,  const float* __restrict__ W2,
                 const float* __restrict__ b1, const float* __restrict__ b2,
                 float* __restrict__ C,
                 int M, int N, int K1, int K2, int cvt)
{
    extern __shared__ uint32_t smem[];
    const uint32_t sbase = (uint32_t)__cvta_generic_to_shared(smem);

    const int tid = threadIdx.x;
    const int w = tid >> 5;
    const int lane = tid & 31;
    const int lg = lane >> 2;
    const int lk = lane & 3;
    const int wm = (w >> 1) * 32;
    const int wn = (w & 1) * 32;
    const int m0 = blockIdx.y * 128;
    const int n0 = blockIdx.x * 64;

    // ldmatrix lane roles
    const int g8 = lane >> 3, r8 = lane & 7;
    const int ghf = g8 >> 1, glf = g8 & 1;

    uint32_t offA[2], offB[2];
#pragma unroll
    for (int im = 0; im < 2; im++)
        offA[im] = (uint32_t)((wm + im * 16 + glf * 8 + r8) * AST + ghf * 4) * 4u;
#pragma unroll
    for (int p = 0; p < 2; p++)
        offB[p] = A_BYTES + (uint32_t)((wn + p * 16 + ghf * 8 + r8) * AST + glf * 4) * 4u;

    // cp.async staging roles
    const int ar = tid >> 3;          // 0..31
    const int ac4 = (tid & 7) * 4;    // word 0..28
    uint32_t stA[4], stB[2];
    int bvalid[2];
#pragma unroll
    for (int i = 0; i < 4; i++)
        stA[i] = (uint32_t)((ar + 32 * i) * AST + ac4) * 4u;
#pragma unroll
    for (int i = 0; i < 2; i++) {
        stB[i] = A_BYTES + (uint32_t)((ar + 32 * i) * AST + ac4) * 4u;
        bvalid[i] = (n0 + ar + 32 * i < N) ? 16 : 0;
    }

    float acc[2][4][4];
#pragma unroll
    for (int i = 0; i < 2; i++)
#pragma unroll
        for (int j = 0; j < 4; j++)
#pragma unroll
            for (int r = 0; r < 4; r++) acc[i][j][r] = 0.f;

    const int nt = (K1 + K2) >> 5;
    const int nt1 = K1 >> 5;

    ISSUE_TILE(0);

    for (int t = 0; t < nt; t++) {
        CP_WAIT0();
        __syncthreads();
        if (t + 1 < nt) ISSUE_TILE(t + 1);

        const uint32_t AbA = sbase + (t & 1) * STAGE_BYTES;
#pragma unroll
        for (int kk = 0; kk < 4; kk++) {
            uint32_t af[2][4];
            uint32_t bf[4][2];
#pragma unroll
            for (int im = 0; im < 2; im++)
                ldsm4(af[im][0], af[im][1], af[im][2], af[im][3],
                      AbA + offA[im] + kk * 32);
#pragma unroll
            for (int p = 0; p < 2; p++)
                ldsm4(bf[2 * p][0], bf[2 * p][1], bf[2 * p + 1][0], bf[2 * p + 1][1],
                      AbA + offB[p] + kk * 32);
#pragma unroll
            for (int im = 0; im < 2; im++)
#pragma unroll
                for (int jn = 0; jn < 4; jn++)
                    mma_tf32(acc[im][jn], af[im], bf[jn]);
        }
    }

    // ---- epilogue ----
#pragma unroll
    for (int im = 0; im < 2; im++) {
#pragma unroll
        for (int jn = 0; jn < 4; jn++) {
            int col0 = n0 + wn + jn * 8 + 2 * lk;
            if (col0 >= N) continue;
            float bias0 = 0.f, bias1 = 0.f;
            if (b1) { bias0 += b1[col0]; bias1 += b1[col0 + 1]; }
            if (b2) { bias0 += b2[col0]; bias1 += b2[col0 + 1]; }
#pragma unroll
            for (int half = 0; half < 2; half++) {
                int row = m0 + wm + im * 16 + lg + half * 8;
                float v0 = acc[im][jn][half * 2 + 0] + bias0;
                float v1 = acc[im][jn][half * 2 + 1] + bias1;
                if (cvt) {
                    v0 = __uint_as_float(f2tf32(v0));
                    v1 = __uint_as_float(f2tf32(v1));
                }
                *reinterpret_cast<float2*>(C + (size_t)row * N + col0) = make_float2(v0, v1);
            }
        }
    }
}

// ---------------- fused LayerNorm + exact GELU (in place, writes tf32) ----
__device__ __forceinline__ float gelu_exact(float x) {
    return 0.5f * x * (1.0f + erff(x * 0.70710678118654752440f));
}

__global__ void ln_gelu_kernel(float* __restrict__ X,
                               const float* __restrict__ g,
                               const float* __restrict__ b,
                               int D)
{
    __shared__ float sS[8], sQ[8];
    float* row = X + (size_t)blockIdx.x * D;
    const int t = threadIdx.x;
    const int w = t >> 5;
    const int lane = t & 31;

    float v0 = row[t];
    float v1 = (D > 256) ? row[t + 256] : 0.f;

    float s = v0 + v1;
    float q = v0 * v0 + v1 * v1;
#pragma unroll
    for (int o = 16; o; o >>= 1) {
        s += __shfl_xor_sync(0xffffffffu, s, o);
        q += __shfl_xor_sync(0xffffffffu, q, o);
    }
    if (lane == 0) { sS[w] = s; sQ[w] = q; }
    __syncthreads();
    float ts = 0.f, tq = 0.f;
#pragma unroll
    for (int i = 0; i < 8; i++) { ts += sS[i]; tq += sQ[i]; }
    float mean = ts / (float)D;
    float var = tq / (float)D - mean * mean;
    float rstd = rsqrtf(var + 1e-5f);

    row[t] = __uint_as_float(f2tf32(gelu_exact((v0 - mean) * rstd * g[t] + b[t])));
    if (D > 256)
        row[t + 256] = __uint_as_float(f2tf32(gelu_exact((v1 - mean) * rstd * g[t + 256] + b[t + 256])));
}

// ---------------- pack adjacency into bitmasks ------------------------------
__global__ void pack_adj_kernel(const int* __restrict__ adj, uint32_t* __restrict__ mb)
{
    int row = blockIdx.x;
    int t = threadIdx.x;
    int v = adj[(size_t)row * NN + t];
    unsigned bal = __ballot_sync(0xffffffffu, v != 0);
    if ((t & 31) == 0) mb[row * (NN / 32) + (t >> 5)] = bal;
}

// ---------------- GAT left/right scores -------------------------------------
__global__ void lr_kernel(const float* __restrict__ Wh,
                          const float* __restrict__ a,
                          float* __restrict__ hl,
                          float* __restrict__ hr)
{
    const int token = blockIdx.x;
    const int w = threadIdx.x >> 5;
    const int lane = threadIdx.x & 31;
    const int head = w >> 1;
    const int side = w & 1;

    const float* whp = Wh + (size_t)token * HID + head * HD;
    const float* ap = a + head * (2 * HD) + side * HD;
    float s = whp[lane] * ap[lane] + whp[lane + 32] * ap[lane + 32];
#pragma unroll
    for (int o = 16; o; o >>= 1) s += __shfl_xor_sync(0xffffffffu, s, o);
    if (lane == 0) {
        int bidx = token >> 9;
        int i = token & 511;
        float* dst = side ? hr : hl;
        dst[((bidx * HEADS + head) << 9) + i] = s;
    }
}

// ---------------- GAT attention: exp-factorized + tf32 MMA ------------------
__global__ void gat_attn_mma_kernel(const float* __restrict__ Wh,
                                    const float* __restrict__ hl,
                                    const float* __restrict__ hr,
                                    const uint32_t* __restrict__ mb,
                                    float* __restrict__ out)
{
    __shared__ float4 sJF[NN];
    __shared__ float sA1[128], sA2[128], sNL[128];
    __shared__ uint4 sP[4 * 8 * 32];
    __shared__ uint32_t sW[32][68];
    __shared__ float sS[128];
    __shared__ float sRed[16];
    __shared__ float sMax[2];

    const int bx = blockIdx.x;
    const int it = bx & 3;
    const int h = (bx >> 2) & 3;
    const int b = bx >> 4;
    const int tid = threadIdx.x;
    const int w = tid >> 5;
    const int lane = tid & 31;
    const int lg = lane >> 2;
    const int lk = lane & 3;
    const int bh = b * HEADS + h;
    const int i0 = it * 128;

    float lv = 0.f;
    if (tid < 128) lv = hl[(bh << 9) + i0 + tid];
    float rv0 = hr[(bh << 9) + tid];
    float rv1 = hr[(bh << 9) + 256 + tid];

    float lm = (tid < 128) ? lv : -INFINITY;
    float rm = fmaxf(rv0, rv1);
#pragma unroll
    for (int o = 16; o; o >>= 1) {
        lm = fmaxf(lm, __shfl_xor_sync(0xffffffffu, lm, o));
        rm = fmaxf(rm, __shfl_xor_sync(0xffffffffu, rm, o));
    }
    if (lane == 0) { sRed[w] = lm; sRed[8 + w] = rm; }
    __syncthreads();
    if (tid == 0) {
        float L = -INFINITY, R = -INFINITY;
#pragma unroll
        for (int q = 0; q < 8; q++) { L = fmaxf(L, sRed[q]); R = fmaxf(R, sRed[8 + q]); }
        sMax[0] = L; sMax[1] = R;
    }
    __syncthreads();
    const float Lmax = sMax[0], Rmax = sMax[1];
    const float C1 = Lmax + Rmax;

    sJF[tid]       = make_float4(rv0, expf(rv0 - Rmax), expf(0.2f * rv0), 0.f);
    sJF[tid + 256] = make_float4(rv1, expf(rv1 - Rmax), expf(0.2f * rv1), 0.f);
    if (tid < 128) {
        sA1[tid] = expf(lv - Lmax);
        sA2[tid] = expf(0.2f * lv - C1);
        sNL[tid] = -lv;
    }
    __syncthreads();

    const int r0 = w * 16 + lg;
    const int r1 = r0 + 8;
    const float A1a = sA1[r0], A2a = sA2[r0], NLa = sNL[r0];
    const float A1b = sA1[r1], A2b = sA2[r1], NLb = sNL[r1];
    const uint32_t* mrow0 = mb + ((size_t)(b << 9) + i0 + r0) * (NN / 32);
    const uint32_t* mrow1 = mb + ((size_t)(b << 9) + i0 + r1) * (NN / 32);
    float psum0 = 0.f, psum1 = 0.f;

    const int wm16 = (w >> 1) * 2;
    const int wn = (w & 1) * 32;
    float acc[2][4][4];
#pragma unroll
    for (int i = 0; i < 2; i++)
#pragma unroll
        for (int j = 0; j < 4; j++)
#pragma unroll
            for (int r = 0; r < 4; r++) acc[i][j][r] = 0.f;

    const float* whbase = Wh + (size_t)b * NN * HID + h * HD;

    for (int jt = 0; jt < 16; jt++) {
#pragma unroll
        for (int itr = 0; itr < 2; itr++) {
            int f = tid + 256 * itr;
            int jp = f >> 4;
            int dq = (f & 15) * 4;
            float4 v = *reinterpret_cast<const float4*>(whbase + (size_t)(jt * 32 + jp) * HID + dq);
            sW[jp][dq + 0] = f2tf32(v.x);
            sW[jp][dq + 1] = f2tf32(v.y);
            sW[jp][dq + 2] = f2tf32(v.z);
            sW[jp][dq + 3] = f2tf32(v.w);
        }
        uint32_t mw0 = mrow0[jt];
        uint32_t mw1 = mrow1[jt];
#pragma unroll
        for (int kk = 0; kk < 4; kk++) {
            int c0 = kk * 8 + lk;
            int c1 = c0 + 4;
            float4 jf0 = sJF[jt * 32 + c0];
            float4 jf1 = sJF[jt * 32 + c1];
            bool cd00 = (jf0.x >= NLa), cd10 = (jf0.x >= NLb);
            bool cd01 = (jf1.x >= NLa), cd11 = (jf1.x >= NLb);
            float p00 = ((mw0 >> c0) & 1) ? (cd00 ? A1a * jf0.y : A2a * jf0.z) : 0.f;
            float p10 = ((mw1 >> c0) & 1) ? (cd10 ? A1b * jf0.y : A2b * jf0.z) : 0.f;
            float p01 = ((mw0 >> c1) & 1) ? (cd01 ? A1a * jf1.y : A2a * jf1.z) : 0.f;
            float p11 = ((mw1 >> c1) & 1) ? (cd11 ? A1b * jf1.y : A2b * jf1.z) : 0.f;
            psum0 += p00 + p01;
            psum1 += p10 + p11;
            uint4 pk;
            pk.x = f2tf32(p00);
            pk.y = f2tf32(p10);
            pk.z = f2tf32(p01);
            pk.w = f2tf32(p11);
            sP[(kk * 8 + w) * 32 + lane] = pk;
        }
        __syncthreads();

#pragma unroll
        for (int kk = 0; kk < 4; kk++) {
            uint4 av[2];
#pragma unroll
            for (int im = 0; im < 2; im++)
                av[im] = sP[(kk * 8 + wm16 + im) * 32 + lane];
#pragma unroll
            for (int jn = 0; jn < 4; jn++) {
                int nc = wn + jn * 8 + lg;
                uint32_t bf[2];
                bf[0] = sW[kk * 8 + lk][nc];
                bf[1] = sW[kk * 8 + 4 + lk][nc];
#pragma unroll
                for (int im = 0; im < 2; im++)
                    mma_tf32(acc[im][jn],
                             reinterpret_cast<const uint32_t*>(&av[im]), bf);
            }
        }
        __syncthreads();
    }

    psum0 += __shfl_xor_sync(0xffffffffu, psum0, 1);
    psum0 += __shfl_xor_sync(0xffffffffu, psum0, 2);
    psum1 += __shfl_xor_sync(0xffffffffu, psum1, 1);
    psum1 += __shfl_xor_sync(0xffffffffu, psum1, 2);
    if (lk == 0) { sS[r0] = psum0; sS[r1] = psum1; }
    __syncthreads();

#pragma unroll
    for (int im = 0; im < 2; im++) {
#pragma unroll
        for (int half = 0; half < 2; half++) {
            int rloc = (w >> 1) * 32 + im * 16 + lg + half * 8;
            float inv = 1.f / sS[rloc];
            int grow = (b << 9) + i0 + rloc;
#pragma unroll
            for (int jn = 0; jn < 4; jn++) {
                int col = wn + jn * 8 + 2 * lk;
                float2* dst = reinterpret_cast<float2*>(out + (size_t)grow * HID + h * HD + col);
                // store tf32-rounded (aout feeds a GEMM)
                *dst = make_float2(
                    __uint_as_float(f2tf32(acc[im][jn][half * 2 + 0] * inv)),
                    __uint_as_float(f2tf32(acc[im][jn][half * 2 + 1] * inv)));
            }
        }
    }
}

// ---------------- GRU gates -> h_temp (fp32 out + tf32 copy) ----------
__global__ void gru_kernel(const float* __restrict__ gsum,
                           const float* __restrict__ in_,
                           const float* __restrict__ hn_,
                           const float* __restrict__ hidden,
                           float* __restrict__ h_temp,
                           float* __restrict__ htc)
{
    int idx = blockIdx.x * blockDim.x + threadIdx.x;
    if (idx >= TOK * HID) return;
    int row = idx >> 8;
    int c = idx & 255;
    const float* gs = gsum + ((size_t)row << 9);
    float r = 1.f / (1.f + expf(-gs[c]));
    float z = 1.f / (1.f + expf(-gs[HID + c]));
    float n = tanhf(in_[idx] + r * hn_[idx]);
    float v = (1.f - z) * n + z * hidden[idx];
    h_temp[idx] = v;
    htc[idx] = __uint_as_float(f2tf32(v));
}

// ---------------- launch ----------------
extern "C" void kernel_launch(void* const* d_in, const int* in_sizes, int n_in,
                              void* d_out, int out_size)
{
    const float* x        = (const float*)d_in[0];
    const int*   adj      = (const int*)  d_in[1];
    const float* hidden   = (const float*)d_in[2];
    const float* enc_w1   = (const float*)d_in[3];
    const float* enc_b1   = (const float*)d_in[4];
    const float* ln1_g    = (const float*)d_in[5];
    const float* ln1_b    = (const float*)d_in[6];
    const float* enc_w2   = (const float*)d_in[7];
    const float* enc_b2   = (const float*)d_in[8];
    const float* pos      = (const float*)d_in[9];
    const float* gat_w    = (const float*)d_in[10];
    const float* gat_b    = (const float*)d_in[11];
    const float* gat_a    = (const float*)d_in[12];
    const float* gat_ow   = (const float*)d_in[13];
    const float* gat_ob   = (const float*)d_in[14];
    const float* skip_w   = (const float*)d_in[15];
    const float* skip_b   = (const float*)d_in[16];
    const float* gru_wih  = (const float*)d_in[17];
    const float* gru_bih  = (const float*)d_in[18];
    const float* gru_whh  = (const float*)d_in[19];
    const float* gru_bhh  = (const float*)d_in[20];
    const float* dec_w1   = (const float*)d_in[21];
    const float* dec_b1   = (const float*)d_in[22];
    const float* ln2_g    = (const float*)d_in[23];
    const float* ln2_b    = (const float*)d_in[24];
    const float* dec_w2   = (const float*)d_in[25];
    const float* dec_b2   = (const float*)d_in[26];

    float* out = (float*)d_out;
    float* q_out = out;
    float* h_temp_out = out + (size_t)TOK * ACT;

    float *h1, *hsp, *Wh, *hl, *hr, *aout, *hattn, *gsum, *in_, *hn_, *q;
    float *xc, *hidc, *htc, *wc;
    uint32_t* mbits;
    cudaGetSymbolAddress((void**)&h1,    g_h1);
    cudaGetSymbolAddress((void**)&hsp,   g_hsp);
    cudaGetSymbolAddress((void**)&Wh,    g_Wh);
    cudaGetSymbolAddress((void**)&hl,    g_hl);
    cudaGetSymbolAddress((void**)&hr,    g_hr);
    cudaGetSymbolAddress((void**)&aout,  g_aout);
    cudaGetSymbolAddress((void**)&hattn, g_hattn);
    cudaGetSymbolAddress((void**)&gsum,  g_gsum);
    cudaGetSymbolAddress((void**)&in_,   g_in_);
    cudaGetSymbolAddress((void**)&hn_,   g_hn_);
    cudaGetSymbolAddress((void**)&q,     g_q);
    cudaGetSymbolAddress((void**)&xc,    g_xc);
    cudaGetSymbolAddress((void**)&hidc,  g_hidc);
    cudaGetSymbolAddress((void**)&htc,   g_htc);
    cudaGetSymbolAddress((void**)&wc,    g_wc);
    cudaGetSymbolAddress((void**)&mbits, g_mbits);

    cudaFuncSetAttribute(gemm_tf32_kernel,
                         cudaFuncAttributeMaxDynamicSharedMemorySize,
                         GEMM_SMEM_BYTES);

    const int MB = TOK / 128;
    const size_t SH = GEMM_SMEM_BYTES;

    // one-shot conversions + adjacency packing
    cvt_all_kernel<<<(1787904 + 255) / 256, 256>>>(
        x, hidden, enc_w1, enc_w2, gat_w, gat_ow, skip_w, gru_wih, gru_whh,
        dec_w1, dec_w2, xc, hidc, wc);
    pack_adj_kernel<<<TOK, 512>>>(adj, mbits);

    // encoder
    gemm_tf32_kernel<<<dim3(HID2 / 64, MB), 256, SH>>>(
        xc, nullptr, wc + WC_ENC1, nullptr, enc_b1, nullptr, h1, TOK, HID2, IND, 0, 0);
    ln_gelu_kernel<<<TOK, 256>>>(h1, ln1_g, ln1_b, HID2);
    gemm_tf32_kernel<<<dim3(HID / 64, MB), 256, SH>>>(
        h1, nullptr, wc + WC_ENC2, nullptr, enc_b2, pos, hsp, TOK, HID, HID2, 0, 1);

    // GAT
    gemm_tf32_kernel<<<dim3(HID / 64, MB), 256, SH>>>(
        hsp, nullptr, wc + WC_GAT, nullptr, gat_b, nullptr, Wh, TOK, HID, HID, 0, 1);
    lr_kernel<<<TOK, 256>>>(Wh, gat_a, hl, hr);
    gat_attn_mma_kernel<<<BB * HEADS * 4, 256>>>(Wh, hl, hr, mbits, aout);

    // fused out-proj + skip
    gemm_tf32_kernel<<<dim3(HID / 64, MB), 256, SH>>>(
        aout, hsp, wc + WC_OW, wc + WC_SKIP, gat_ob, skip_b, hattn, TOK, HID, HID, HID, 1);

    // GRU: fused r,z over K-concat; separate i_n, h_n
    gemm_tf32_kernel<<<dim3(HID2 / 64, MB), 256, SH>>>(
        hattn, hidc, wc + WC_WIH, wc + WC_WHH, gru_bih, gru_bhh, gsum, TOK, HID2, HID, HID, 0);
    gemm_tf32_kernel<<<dim3(HID / 64, MB), 256, SH>>>(
        hattn, nullptr, wc + WC_WIH + 2 * HID * HID, nullptr, gru_bih + 2 * HID, nullptr,
        in_, TOK, HID, HID, 0, 0);
    gemm_tf32_kernel<<<dim3(HID / 64, MB), 256, SH>>>(
        hidc, nullptr, wc + WC_WHH + 2 * HID * HID, nullptr, gru_bhh + 2 * HID, nullptr,
        hn_, TOK, HID, HID, 0, 0);
    gru_kernel<<<(TOK * HID + 255) / 256, 256>>>(gsum, in_, hn_, hidden, h_temp_out, htc);

    // decoder
    gemm_tf32_kernel<<<dim3(HID / 64, MB), 256, SH>>>(
        htc, nullptr, wc + WC_DEC1, nullptr, dec_b1, nullptr, q, TOK, HID, HID, 0, 0);
    ln_gelu_kernel<<<TOK, 256>>>(q, ln2_g, ln2_b, HID);
    gemm_tf32_kernel<<<dim3(1, MB), 256, SH>>>(
        q, nullptr, wc + WC_DEC2, nullptr, dec_b2, nullptr, q_out, TOK, ACT, HID, 0, 0);
}

// round 10
// speedup vs baseline: 5.3479x; 1.0317x over previous
#include <cuda_runtime.h>
#include <math.h>
#include <stdint.h>

// ---------------- problem constants ----------------
#define BB   32
#define NN   512
#define IND  128
#define HID  256
#define HID2 512
#define HEADS 4
#define HD   64
#define ACT  32
#define TOK  (BB*NN)            // 16384 tokens

// GEMM smem geometry: [row][k] stride-36 words, double buffered
#define AST  36
#define A_WORDS (128 * AST)
#define W_WORDS (64 * AST)
#define A_BYTES (A_WORDS * 4)
#define STAGE_BYTES ((A_WORDS + W_WORDS) * 4)     // 27648
#define GEMM_SMEM_BYTES (2 * STAGE_BYTES)         // 55296

// ---------------- scratch (device globals) --------
__device__ float g_h1[TOK * HID2];
__device__ float g_hsp[TOK * HID];
__device__ float g_Wh[TOK * HID];
__device__ float g_hl[BB * HEADS * NN];
__device__ float g_hr[BB * HEADS * NN];
__device__ float g_aout[TOK * HID];
__device__ float g_hattn[TOK * HID];
__device__ float g_gg[TOK * 1024];         // merged GRU gates: [rz(512) | in(256) | hn(256)]
__device__ float g_q[TOK * HID];
__device__ float g_xc[TOK * IND];
__device__ float g_hidc[TOK * HID];
__device__ float g_htc[TOK * HID];
__device__ float g_wc[860160];
__device__ uint32_t g_mbits[(size_t)BB * NN * (NN / 32)];

// weight offsets in g_wc (floats)
#define WC_ENC1 0
#define WC_ENC2 65536
#define WC_GAT  196608
#define WC_OW   262144
#define WC_SKIP 327680
#define WC_WIH  393216
#define WC_WHH  589824
#define WC_DEC1 786432
#define WC_DEC2 851968

// ---------------- helpers ----------------
__device__ __forceinline__ uint32_t f2tf32(float f) {
    uint32_t r;
    asm("cvt.rna.tf32.f32 %0, %1;" : "=r"(r) : "f"(f));
    return r;
}

__device__ __forceinline__ void mma_tf32(float* d, const uint32_t* a, const uint32_t* b) {
    asm volatile(
        "mma.sync.aligned.m16n8k8.row.col.f32.tf32.tf32.f32 "
        "{%0,%1,%2,%3},{%4,%5,%6,%7},{%8,%9},{%0,%1,%2,%3};"
        : "+f"(d[0]), "+f"(d[1]), "+f"(d[2]), "+f"(d[3])
        : "r"(a[0]), "r"(a[1]), "r"(a[2]), "r"(a[3]),
          "r"(b[0]), "r"(b[1]));
}

__device__ __forceinline__ void ldsm4(uint32_t& r0, uint32_t& r1, uint32_t& r2, uint32_t& r3,
                                      uint32_t addr) {
    asm volatile("ldmatrix.sync.aligned.m8n8.x4.shared.b16 {%0,%1,%2,%3}, [%4];"
                 : "=r"(r0), "=r"(r1), "=r"(r2), "=r"(r3) : "r"(addr));
}

__device__ __forceinline__ void cpa16(uint32_t dst, const void* src, int srcsize) {
    asm volatile("cp.async.ca.shared.global [%0], [%1], 16, %2;"
                 :: "r"(dst), "l"(src), "r"(srcsize) : "memory");
}
#define CP_COMMIT() asm volatile("cp.async.commit_group;" ::: "memory")
#define CP_WAIT0()  asm volatile("cp.async.wait_group 0;" ::: "memory")

// ---------------- merged prep: tf32 conversions + adjacency packing ---------
#define CVT_BLOCKS 3492    // 1787904 float4 / 512
__global__ void prep_kernel(const float* __restrict__ x, const float* __restrict__ hidden,
    const float* __restrict__ w_e1, const float* __restrict__ w_e2,
    const float* __restrict__ w_g,  const float* __restrict__ w_ow,
    const float* __restrict__ w_sk, const float* __restrict__ w_ih,
    const float* __restrict__ w_hh, const float* __restrict__ w_d1,
    const float* __restrict__ w_d2,
    float* __restrict__ xc, float* __restrict__ hidc, float* __restrict__ wc,
    const int* __restrict__ adj, uint32_t* __restrict__ mb)
{
    if (blockIdx.x >= CVT_BLOCKS) {
        int row = blockIdx.x - CVT_BLOCKS;
        int t = threadIdx.x;
        int v = adj[(size_t)row * NN + t];
        unsigned bal = __ballot_sync(0xffffffffu, v != 0);
        if ((t & 31) == 0) mb[row * (NN / 32) + (t >> 5)] = bal;
        return;
    }
    const int NX = 524288, NH = 1048576;   // float4 counts
    int i = blockIdx.x * 512 + threadIdx.x;
    const float4* src; float4* dst;
    if (i < NX) { src = (const float4*)x + i; dst = (float4*)xc + i; }
    else if (i < NX + NH) { int j = i - NX; src = (const float4*)hidden + j; dst = (float4*)hidc + j; }
    else {
        int j = i - (NX + NH);
        const float* s; int o;
        if      (j < 16384)  { s = w_e1; o = j; }
        else if (j < 49152)  { s = w_e2; o = j - 16384; }
        else if (j < 65536)  { s = w_g;  o = j - 49152; }
        else if (j < 81920)  { s = w_ow; o = j - 65536; }
        else if (j < 98304)  { s = w_sk; o = j - 81920; }
        else if (j < 147456) { s = w_ih; o = j - 98304; }
        else if (j < 196608) { s = w_hh; o = j - 147456; }
        else if (j < 212992) { s = w_d1; o = j - 196608; }
        else                 { s = w_d2; o = j - 212992; }
        src = (const float4*)s + o; dst = (float4*)wc + j;
    }
    float4 v = *src;
    float4 r;
    r.x = __uint_as_float(f2tf32(v.x));
    r.y = __uint_as_float(f2tf32(v.y));
    r.z = __uint_as_float(f2tf32(v.z));
    r.w = __uint_as_float(f2tf32(v.w));
    *dst = r;
}

// ---------------- segmented TF32 NT GEMM ------------------------------------
// Up to 3 column segments, each its own A/A2/W/W2/b1/b2/K1/K2/cvt/N.
// C row stride = NTOT. Block bx covers global cols [bx*64, bx*64+64).
// Optional lr fusion (gat launch): per-block head = nloc, computes hl/hr.
struct Seg {
    const float *A, *A2, *W, *W2, *b1, *b2;
    int K1, K2, cvt, N;
};

#define ISSUE_TILE(t_) do {                                                    \
    int _t = (t_);                                                             \
    const float* _Ap; const float* _Wp; int _lda, _kof;                        \
    if (_t < nt1) { _Ap = Aq; _Wp = Wq; _lda = K1; _kof = _t * 32; }           \
    else { _Ap = A2q; _Wp = W2q; _lda = K2; _kof = _t * 32 - K1; }             \
    _kof += ac4;                                                               \
    uint32_t _sb = sbase + (_t & 1) * STAGE_BYTES;                             \
    _Pragma("unroll")                                                          \
    for (int _i = 0; _i < 4; _i++)                                             \
        cpa16(_sb + stA[_i], _Ap + (size_t)(m0 + ar + 32 * _i) * _lda + _kof, 16); \
    _Pragma("unroll")                                                          \
    for (int _i = 0; _i < 2; _i++)                                             \
        cpa16(_sb + stB[_i], _Wp + (size_t)(n0l + ar + 32 * _i) * _lda + _kof, bvalid[_i]); \
    CP_COMMIT();                                                               \
} while (0)

__global__ void __launch_bounds__(256, 3)
gemm_tf32_kernel(Seg s0, Seg s1, Seg s2, int nb1, int nb2,
                 float* __restrict__ C, int NTOT, int M,
                 const float* __restrict__ lr_a,
                 float* __restrict__ hl, float* __restrict__ hr)
{
    extern __shared__ uint32_t smem[];
    __shared__ float sAL[64], sAR[64];
    __shared__ float sLR[2][128][2];
    const uint32_t sbase = (uint32_t)__cvta_generic_to_shared(smem);

    const int bx = blockIdx.x;
    Seg sg; int nloc;
    if (bx >= nb2)      { sg = s2; nloc = bx - nb2; }
    else if (bx >= nb1) { sg = s1; nloc = bx - nb1; }
    else                { sg = s0; nloc = bx; }
    const float *Aq = sg.A, *A2q = sg.A2, *Wq = sg.W, *W2q = sg.W2;
    const float *b1 = sg.b1, *b2 = sg.b2;
    const int K1 = sg.K1, K2 = sg.K2, cvt = sg.cvt, segN = sg.N;

    const int tid = threadIdx.x;
    const int w = tid >> 5;
    const int lane = tid & 31;
    const int lg = lane >> 2;
    const int lk = lane & 3;
    const int wm = (w >> 1) * 32;
    const int wn = (w & 1) * 32;
    const int m0 = blockIdx.y * 128;
    const int n0g = bx * 64;           // global C col base
    const int n0l = nloc * 64;         // segment-local col base

    if (lr_a && tid < 128) {
        if (tid < 64) sAL[tid] = lr_a[nloc * 128 + tid];
        else          sAR[tid - 64] = lr_a[nloc * 128 + tid];
    }

    // ldmatrix lane roles
    const int g8 = lane >> 3, r8 = lane & 7;
    const int ghf = g8 >> 1, glf = g8 & 1;

    uint32_t offA[2], offB[2];
#pragma unroll
    for (int im = 0; im < 2; im++)
        offA[im] = (uint32_t)((wm + im * 16 + glf * 8 + r8) * AST + ghf * 4) * 4u;
#pragma unroll
    for (int p = 0; p < 2; p++)
        offB[p] = A_BYTES + (uint32_t)((wn + p * 16 + ghf * 8 + r8) * AST + glf * 4) * 4u;

    // cp.async staging roles
    const int ar = tid >> 3;
    const int ac4 = (tid & 7) * 4;
    uint32_t stA[4], stB[2];
    int bvalid[2];
#pragma unroll
    for (int i = 0; i < 4; i++)
        stA[i] = (uint32_t)((ar + 32 * i) * AST + ac4) * 4u;
#pragma unroll
    for (int i = 0; i < 2; i++) {
        stB[i] = A_BYTES + (uint32_t)((ar + 32 * i) * AST + ac4) * 4u;
        bvalid[i] = (n0l + ar + 32 * i < segN) ? 16 : 0;
    }

    float acc[2][4][4];
#pragma unroll
    for (int i = 0; i < 2; i++)
#pragma unroll
        for (int j = 0; j < 4; j++)
#pragma unroll
            for (int r = 0; r < 4; r++) acc[i][j][r] = 0.f;

    const int nt = (K1 + K2) >> 5;
    const int nt1 = K1 >> 5;

    ISSUE_TILE(0);

    for (int t = 0; t < nt; t++) {
        CP_WAIT0();
        __syncthreads();
        if (t + 1 < nt) ISSUE_TILE(t + 1);

        const uint32_t AbA = sbase + (t & 1) * STAGE_BYTES;
#pragma unroll
        for (int kk = 0; kk < 4; kk++) {
            uint32_t af[2][4];
            uint32_t bf[4][2];
#pragma unroll
            for (int im = 0; im < 2; im++)
                ldsm4(af[im][0], af[im][1], af[im][2], af[im][3],
                      AbA + offA[im] + kk * 32);
#pragma unroll
            for (int p = 0; p < 2; p++)
                ldsm4(bf[2 * p][0], bf[2 * p][1], bf[2 * p + 1][0], bf[2 * p + 1][1],
                      AbA + offB[p] + kk * 32);
#pragma unroll
            for (int im = 0; im < 2; im++)
#pragma unroll
                for (int jn = 0; jn < 4; jn++)
                    mma_tf32(acc[im][jn], af[im], bf[jn]);
        }
    }

    // ---- epilogue (+ optional lr dot accumulation) ----
    float pl[2][2] = {{0.f, 0.f}, {0.f, 0.f}};
    float pr[2][2] = {{0.f, 0.f}, {0.f, 0.f}};
#pragma unroll
    for (int im = 0; im < 2; im++) {
#pragma unroll
        for (int jn = 0; jn < 4; jn++) {
            int colL = wn + jn * 8 + 2 * lk;           // segment-local col
            if (n0l + colL >= segN) continue;
            float bias0 = 0.f, bias1 = 0.f;
            if (b1) { bias0 += b1[n0l + colL]; bias1 += b1[n0l + colL + 1]; }
            if (b2) { bias0 += b2[n0l + colL]; bias1 += b2[n0l + colL + 1]; }
#pragma unroll
            for (int half = 0; half < 2; half++) {
                int row = m0 + wm + im * 16 + lg + half * 8;
                float v0 = acc[im][jn][half * 2 + 0] + bias0;
                float v1 = acc[im][jn][half * 2 + 1] + bias1;
                if (lr_a) {
                    pl[im][half] += v0 * sAL[colL] + v1 * sAL[colL + 1];
                    pr[im][half] += v0 * sAR[colL] + v1 * sAR[colL + 1];
                }
                if (cvt) {
                    v0 = __uint_as_float(f2tf32(v0));
                    v1 = __uint_as_float(f2tf32(v1));
                }
                *reinterpret_cast<float2*>(C + (size_t)row * NTOT + n0g + colL)
                    = make_float2(v0, v1);
            }
        }
    }

    if (lr_a) {
        // reduce over lk (lanes sharing lg)
#pragma unroll
        for (int im = 0; im < 2; im++)
#pragma unroll
            for (int half = 0; half < 2; half++) {
                pl[im][half] += __shfl_xor_sync(0xffffffffu, pl[im][half], 1);
                pl[im][half] += __shfl_xor_sync(0xffffffffu, pl[im][half], 2);
                pr[im][half] += __shfl_xor_sync(0xffffffffu, pr[im][half], 1);
                pr[im][half] += __shfl_xor_sync(0xffffffffu, pr[im][half], 2);
            }
        if (lk == 0) {
#pragma unroll
            for (int im = 0; im < 2; im++)
#pragma unroll
                for (int half = 0; half < 2; half++) {
                    int rl = wm + im * 16 + lg + half * 8;
                    sLR[0][rl][w & 1] = pl[im][half];
                    sLR[1][rl][w & 1] = pr[im][half];
                }
        }
        __syncthreads();
        int s = tid >> 7;         // 0: left, 1: right
        int row = tid & 127;
        float v = sLR[s][row][0] + sLR[s][row][1];
        int grow = m0 + row;
        int bidx = grow >> 9;
        int ii = grow & 511;
        float* dst = s ? hr : hl;
        dst[((bidx * HEADS + nloc) << 9) + ii] = v;
    }
}

// ---------------- fused LayerNorm + exact GELU (in place, writes tf32) ----
__device__ __forceinline__ float gelu_exact(float x) {
    return 0.5f * x * (1.0f + erff(x * 0.70710678118654752440f));
}

__global__ void ln_gelu_kernel(float* __restrict__ X,
                               const float* __restrict__ g,
                               const float* __restrict__ b,
                               int D)
{
    __shared__ float sS[8], sQ[8];
    float* row = X + (size_t)blockIdx.x * D;
    const int t = threadIdx.x;
    const int w = t >> 5;
    const int lane = t & 31;

    float v0 = row[t];
    float v1 = (D > 256) ? row[t + 256] : 0.f;

    float s = v0 + v1;
    float q = v0 * v0 + v1 * v1;
#pragma unroll
    for (int o = 16; o; o >>= 1) {
        s += __shfl_xor_sync(0xffffffffu, s, o);
        q += __shfl_xor_sync(0xffffffffu, q, o);
    }
    if (lane == 0) { sS[w] = s; sQ[w] = q; }
    __syncthreads();
    float ts = 0.f, tq = 0.f;
#pragma unroll
    for (int i = 0; i < 8; i++) { ts += sS[i]; tq += sQ[i]; }
    float mean = ts / (float)D;
    float var = tq / (float)D - mean * mean;
    float rstd = rsqrtf(var + 1e-5f);

    row[t] = __uint_as_float(f2tf32(gelu_exact((v0 - mean) * rstd * g[t] + b[t])));
    if (D > 256)
        row[t + 256] = __uint_as_float(f2tf32(gelu_exact((v1 - mean) * rstd * g[t + 256] + b[t + 256])));
}

// ---------------- GAT attention: exp-factorized + tf32 MMA ------------------
__global__ void gat_attn_mma_kernel(const float* __restrict__ Wh,
                                    const float* __restrict__ hl,
                                    const float* __restrict__ hr,
                                    const uint32_t* __restrict__ mb,
                                    float* __restrict__ out)
{
    __shared__ float4 sJF[NN];
    __shared__ float sA1[128], sA2[128], sNL[128];
    __shared__ uint4 sP[4 * 8 * 32];
    __shared__ uint32_t sW[32][68];
    __shared__ float sS[128];
    __shared__ float sRed[16];
    __shared__ float sMax[2];

    const int bx = blockIdx.x;
    const int it = bx & 3;
    const int h = (bx >> 2) & 3;
    const int b = bx >> 4;
    const int tid = threadIdx.x;
    const int w = tid >> 5;
    const int lane = tid & 31;
    const int lg = lane >> 2;
    const int lk = lane & 3;
    const int bh = b * HEADS + h;
    const int i0 = it * 128;

    float lv = 0.f;
    if (tid < 128) lv = hl[(bh << 9) + i0 + tid];
    float rv0 = hr[(bh << 9) + tid];
    float rv1 = hr[(bh << 9) + 256 + tid];

    float lm = (tid < 128) ? lv : -INFINITY;
    float rm = fmaxf(rv0, rv1);
#pragma unroll
    for (int o = 16; o; o >>= 1) {
        lm = fmaxf(lm, __shfl_xor_sync(0xffffffffu, lm, o));
        rm = fmaxf(rm, __shfl_xor_sync(0xffffffffu, rm, o));
    }
    if (lane == 0) { sRed[w] = lm; sRed[8 + w] = rm; }
    __syncthreads();
    if (tid == 0) {
        float L = -INFINITY, R = -INFINITY;
#pragma unroll
        for (int q = 0; q < 8; q++) { L = fmaxf(L, sRed[q]); R = fmaxf(R, sRed[8 + q]); }
        sMax[0] = L; sMax[1] = R;
    }
    __syncthreads();
    const float Lmax = sMax[0], Rmax = sMax[1];
    const float C1 = Lmax + Rmax;

    sJF[tid]       = make_float4(rv0, expf(rv0 - Rmax), expf(0.2f * rv0), 0.f);
    sJF[tid + 256] = make_float4(rv1, expf(rv1 - Rmax), expf(0.2f * rv1), 0.f);
    if (tid < 128) {
        sA1[tid] = expf(lv - Lmax);
        sA2[tid] = expf(0.2f * lv - C1);
        sNL[tid] = -lv;
    }
    __syncthreads();

    const int r0 = w * 16 + lg;
    const int r1 = r0 + 8;
    const float A1a = sA1[r0], A2a = sA2[r0], NLa = sNL[r0];
    const float A1b = sA1[r1], A2b = sA2[r1], NLb = sNL[r1];
    const uint32_t* mrow0 = mb + ((size_t)(b << 9) + i0 + r0) * (NN / 32);
    const uint32_t* mrow1 = mb + ((size_t)(b << 9) + i0 + r1) * (NN / 32);
    float psum0 = 0.f, psum1 = 0.f;

    const int wm16 = (w >> 1) * 2;
    const int wn = (w & 1) * 32;
    float acc[2][4][4];
#pragma unroll
    for (int i = 0; i < 2; i++)
#pragma unroll
        for (int j = 0; j < 4; j++)
#pragma unroll
            for (int r = 0; r < 4; r++) acc[i][j][r] = 0.f;

    const float* whbase = Wh + (size_t)b * NN * HID + h * HD;

    for (int jt = 0; jt < 16; jt++) {
#pragma unroll
        for (int itr = 0; itr < 2; itr++) {
            int f = tid + 256 * itr;
            int jp = f >> 4;
            int dq = (f & 15) * 4;
            float4 v = *reinterpret_cast<const float4*>(whbase + (size_t)(jt * 32 + jp) * HID + dq);
            sW[jp][dq + 0] = f2tf32(v.x);
            sW[jp][dq + 1] = f2tf32(v.y);
            sW[jp][dq + 2] = f2tf32(v.z);
            sW[jp][dq + 3] = f2tf32(v.w);
        }
        uint32_t mw0 = mrow0[jt];
        uint32_t mw1 = mrow1[jt];
#pragma unroll
        for (int kk = 0; kk < 4; kk++) {
            int c0 = kk * 8 + lk;
            int c1 = c0 + 4;
            float4 jf0 = sJF[jt * 32 + c0];
            float4 jf1 = sJF[jt * 32 + c1];
            bool cd00 = (jf0.x >= NLa), cd10 = (jf0.x >= NLb);
            bool cd01 = (jf1.x >= NLa), cd11 = (jf1.x >= NLb);
            float p00 = ((mw0 >> c0) & 1) ? (cd00 ? A1a * jf0.y : A2a * jf0.z) : 0.f;
            float p10 = ((mw1 >> c0) & 1) ? (cd10 ? A1b * jf0.y : A2b * jf0.z) : 0.f;
            float p01 = ((mw0 >> c1) & 1) ? (cd01 ? A1a * jf1.y : A2a * jf1.z) : 0.f;
            float p11 = ((mw1 >> c1) & 1) ? (cd11 ? A1b * jf1.y : A2b * jf1.z) : 0.f;
            psum0 += p00 + p01;
            psum1 += p10 + p11;
            uint4 pk;
            pk.x = f2tf32(p00);
            pk.y = f2tf32(p10);
            pk.z = f2tf32(p01);
            pk.w = f2tf32(p11);
            sP[(kk * 8 + w) * 32 + lane] = pk;
        }
        __syncthreads();

#pragma unroll
        for (int kk = 0; kk < 4; kk++) {
            uint4 av[2];
#pragma unroll
            for (int im = 0; im < 2; im++)
                av[im] = sP[(kk * 8 + wm16 + im) * 32 + lane];
#pragma unroll
            for (int jn = 0; jn < 4; jn++) {
                int nc = wn + jn * 8 + lg;
                uint32_t bf[2];
                bf[0] = sW[kk * 8 + lk][nc];
                bf[1] = sW[kk * 8 + 4 + lk][nc];
#pragma unroll
                for (int im = 0; im < 2; im++)
                    mma_tf32(acc[im][jn],
                             reinterpret_cast<const uint32_t*>(&av[im]), bf);
            }
        }
        __syncthreads();
    }

    psum0 += __shfl_xor_sync(0xffffffffu, psum0, 1);
    psum0 += __shfl_xor_sync(0xffffffffu, psum0, 2);
    psum1 += __shfl_xor_sync(0xffffffffu, psum1, 1);
    psum1 += __shfl_xor_sync(0xffffffffu, psum1, 2);
    if (lk == 0) { sS[r0] = psum0; sS[r1] = psum1; }
    __syncthreads();

#pragma unroll
    for (int im = 0; im < 2; im++) {
#pragma unroll
        for (int half = 0; half < 2; half++) {
            int rloc = (w >> 1) * 32 + im * 16 + lg + half * 8;
            float inv = 1.f / sS[rloc];
            int grow = (b << 9) + i0 + rloc;
#pragma unroll
            for (int jn = 0; jn < 4; jn++) {
                int col = wn + jn * 8 + 2 * lk;
                float2* dst = reinterpret_cast<float2*>(out + (size_t)grow * HID + h * HD + col);
                *dst = make_float2(
                    __uint_as_float(f2tf32(acc[im][jn][half * 2 + 0] * inv)),
                    __uint_as_float(f2tf32(acc[im][jn][half * 2 + 1] * inv)));
            }
        }
    }
}

// ---------------- GRU gates -> h_temp (fp32 out + tf32 copy) ----------
// gg layout: cols [0,256)=r pre, [256,512)=z pre, [512,768)=i_n, [768,1024)=h_n
__global__ void gru_kernel(const float* __restrict__ gg,
                           const float* __restrict__ hidden,
                           float* __restrict__ h_temp,
                           float* __restrict__ htc)
{
    int idx = blockIdx.x * blockDim.x + threadIdx.x;
    if (idx >= TOK * HID) return;
    int row = idx >> 8;
    int c = idx & 255;
    const float* g = gg + ((size_t)row << 10);
    float r = 1.f / (1.f + expf(-g[c]));
    float z = 1.f / (1.f + expf(-g[256 + c]));
    float n = tanhf(g[512 + c] + r * g[768 + c]);
    float v = (1.f - z) * n + z * hidden[idx];
    h_temp[idx] = v;
    htc[idx] = __uint_as_float(f2tf32(v));
}

// ---------------- launch ----------------
extern "C" void kernel_launch(void* const* d_in, const int* in_sizes, int n_in,
                              void* d_out, int out_size)
{
    const float* x        = (const float*)d_in[0];
    const int*   adj      = (const int*)  d_in[1];
    const float* hidden   = (const float*)d_in[2];
    const float* enc_w1   = (const float*)d_in[3];
    const float* enc_b1   = (const float*)d_in[4];
    const float* ln1_g    = (const float*)d_in[5];
    const float* ln1_b    = (const float*)d_in[6];
    const float* enc_w2   = (const float*)d_in[7];
    const float* enc_b2   = (const float*)d_in[8];
    const float* pos      = (const float*)d_in[9];
    const float* gat_w    = (const float*)d_in[10];
    const float* gat_b    = (const float*)d_in[11];
    const float* gat_a    = (const float*)d_in[12];
    const float* gat_ow   = (const float*)d_in[13];
    const float* gat_ob   = (const float*)d_in[14];
    const float* skip_w   = (const float*)d_in[15];
    const float* skip_b   = (const float*)d_in[16];
    const float* gru_wih  = (const float*)d_in[17];
    const float* gru_bih  = (const float*)d_in[18];
    const float* gru_whh  = (const float*)d_in[19];
    const float* gru_bhh  = (const float*)d_in[20];
    const float* dec_w1   = (const float*)d_in[21];
    const float* dec_b1   = (const float*)d_in[22];
    const float* ln2_g    = (const float*)d_in[23];
    const float* ln2_b    = (const float*)d_in[24];
    const float* dec_w2   = (const float*)d_in[25];
    const float* dec_b2   = (const float*)d_in[26];

    float* out = (float*)d_out;
    float* q_out = out;
    float* h_temp_out = out + (size_t)TOK * ACT;

    float *h1, *hsp, *Wh, *hl, *hr, *aout, *hattn, *gg, *q;
    float *xc, *hidc, *htc, *wc;
    uint32_t* mbits;
    cudaGetSymbolAddress((void**)&h1,    g_h1);
    cudaGetSymbolAddress((void**)&hsp,   g_hsp);
    cudaGetSymbolAddress((void**)&Wh,    g_Wh);
    cudaGetSymbolAddress((void**)&hl,    g_hl);
    cudaGetSymbolAddress((void**)&hr,    g_hr);
    cudaGetSymbolAddress((void**)&aout,  g_aout);
    cudaGetSymbolAddress((void**)&hattn, g_hattn);
    cudaGetSymbolAddress((void**)&gg,    g_gg);
    cudaGetSymbolAddress((void**)&q,     g_q);
    cudaGetSymbolAddress((void**)&xc,    g_xc);
    cudaGetSymbolAddress((void**)&hidc,  g_hidc);
    cudaGetSymbolAddress((void**)&htc,   g_htc);
    cudaGetSymbolAddress((void**)&wc,    g_wc);
    cudaGetSymbolAddress((void**)&mbits, g_mbits);

    cudaFuncSetAttribute(gemm_tf32_kernel,
                         cudaFuncAttributeMaxDynamicSharedMemorySize,
                         GEMM_SMEM_BYTES);

    const int MB = TOK / 128;
    const size_t SH = GEMM_SMEM_BYTES;
    Seg Z = { nullptr, nullptr, nullptr, nullptr, nullptr, nullptr, 0, 0, 0, 0 };

    // prep: tf32 conversions + adjacency pack (one launch)
    prep_kernel<<<CVT_BLOCKS + TOK, 512>>>(
        x, hidden, enc_w1, enc_w2, gat_w, gat_ow, skip_w, gru_wih, gru_whh,
        dec_w1, dec_w2, xc, hidc, wc, adj, mbits);

    // encoder
    {
        Seg s = { xc, nullptr, wc + WC_ENC1, nullptr, enc_b1, nullptr, IND, 0, 0, HID2 };
        gemm_tf32_kernel<<<dim3(8, MB), 256, SH>>>(s, Z, Z, 8, 8, h1, HID2, TOK,
                                                   nullptr, nullptr, nullptr);
    }
    ln_gelu_kernel<<<TOK, 256>>>(h1, ln1_g, ln1_b, HID2);
    {
        Seg s = { h1, nullptr, wc + WC_ENC2, nullptr, enc_b2, pos, HID2, 0, 1, HID };
        gemm_tf32_kernel<<<dim3(4, MB), 256, SH>>>(s, Z, Z, 4, 4, hsp, HID, TOK,
                                                   nullptr, nullptr, nullptr);
    }

    // GAT projection + fused l/r scores
    {
        Seg s = { hsp, nullptr, wc + WC_GAT, nullptr, gat_b, nullptr, HID, 0, 1, HID };
        gemm_tf32_kernel<<<dim3(4, MB), 256, SH>>>(s, Z, Z, 4, 4, Wh, HID, TOK,
                                                   gat_a, hl, hr);
    }
    gat_attn_mma_kernel<<<BB * HEADS * 4, 256>>>(Wh, hl, hr, mbits, aout);

    // fused out-proj + skip
    {
        Seg s = { aout, hsp, wc + WC_OW, wc + WC_SKIP, gat_ob, skip_b, HID, HID, 1, HID };
        gemm_tf32_kernel<<<dim3(4, MB), 256, SH>>>(s, Z, Z, 4, 4, hattn, HID, TOK,
                                                   nullptr, nullptr, nullptr);
    }

    // merged GRU GEMM: [rz(512) | i_n(256) | h_n(256)] -> gg[TOK,1024]
    {
        Seg s0 = { hattn, hidc, wc + WC_WIH, wc + WC_WHH, gru_bih, gru_bhh,
                   HID, HID, 0, HID2 };
        Seg s1 = { hattn, nullptr, wc + WC_WIH + 2 * HID * HID, nullptr,
                   gru_bih + 2 * HID, nullptr, HID, 0, 0, HID };
        Seg s2 = { hidc, nullptr, wc + WC_WHH + 2 * HID * HID, nullptr,
                   gru_bhh + 2 * HID, nullptr, HID, 0, 0, HID };
        gemm_tf32_kernel<<<dim3(16, MB), 256, SH>>>(s0, s1, s2, 8, 12, gg, 1024, TOK,
                                                    nullptr, nullptr, nullptr);
    }
    gru_kernel<<<(TOK * HID + 255) / 256, 256>>>(gg, hidden, h_temp_out, htc);

    // decoder
    {
        Seg s = { htc, nullptr, wc + WC_DEC1, nullptr, dec_b1, nullptr, HID, 0, 0, HID };
        gemm_tf32_kernel<<<dim3(4, MB), 256, SH>>>(s, Z, Z, 4, 4, q, HID, TOK,
                                                   nullptr, nullptr, nullptr);
    }
    ln_gelu_kernel<<<TOK, 256>>>(q, ln2_g, ln2_b, HID);
    {
        Seg s = { q, nullptr, wc + WC_DEC2, nullptr, dec_b2, nullptr, HID, 0, 0, ACT };
        gemm_tf32_kernel<<<dim3(1, MB), 256, SH>>>(s, Z, Z, 1, 1, q_out, ACT, TOK,
                                                   nullptr, nullptr, nullptr);
    }
}